// round 4
// baseline (speedup 1.0000x reference)
#include <cuda_runtime.h>
#include <cuda_bf16.h>
#include <math.h>

// ---------------- problem constants ----------------
#define N0_NODES 20000
#define N_ALL    40000
#define F0_DIM   512
#define HID      64
#define NHEAD    8
#define E_CNT    200000
#define BATCH    8192
#define AV_DIM   128
#define CH_DIM   128

typedef unsigned long long ull;

__device__ __forceinline__ ull pack2(float lo, float hi) {
    ull r; asm("mov.b64 %0, {%1, %2};" : "=l"(r) : "f"(lo), "f"(hi)); return r;
}
__device__ __forceinline__ void unpack2(ull v, float& lo, float& hi) {
    asm("mov.b64 {%0, %1}, %2;" : "=f"(lo), "=f"(hi) : "l"(v));
}
__device__ __forceinline__ void ffma2(ull& d, ull a, ull b) {
    asm("fma.rn.f32x2 %0, %1, %2, %0;" : "+l"(d) : "l"(a), "l"(b));
}
__device__ __forceinline__ ull fadd2(ull a, ull b) {
    ull r; asm("add.rn.f32x2 %0, %1, %2;" : "=l"(r) : "l"(a), "l"(b)); return r;
}
__device__ __forceinline__ void cpa16(unsigned dst, const float* src, bool valid) {
    int sz = valid ? 16 : 0;
    asm volatile("cp.async.cg.shared.global [%0], [%1], 16, %2;" :: "r"(dst), "l"(src), "r"(sz));
}
#define CP_COMMIT() asm volatile("cp.async.commit_group;")
#define CP_WAIT1()  asm volatile("cp.async.wait_group 1;")
#define CP_WAIT0()  asm volatile("cp.async.wait_group 0;")

// ---------------- device scratch ----------------
__device__ __align__(16) float g_feat[N_ALL * HID];
__device__ __align__(16) float g_fr[4 * 3 * HID];
__device__ __align__(16) float g_s[4 * BATCH * NHEAD];
__device__ __align__(16) float g_ret[4 * BATCH * HID];
__device__ __align__(16) float g_mpout[4 * BATCH * HID];
__device__ __align__(16) float g_sem[4];

// ---------------- rotation precompute ----------------
__global__ void k_fr(const float* __restrict__ r_vec) {
    int tid = threadIdx.x;
    if (tid >= 128) return;
    int mp = tid >> 5, c = tid & 31;
    int et0 = (mp < 2) ? 0 : 1;
    int et1 = (mp < 2) ? 1 : 0;

    float x0 = r_vec[(et1 >> 1) * 64 + 2 * c], y0 = r_vec[(et1 >> 1) * 64 + 2 * c + 1];
    float n = rsqrtf(x0 * x0 + y0 * y0);
    float f1re = x0 * n, f1im = (et1 & 1) ? -y0 * n : y0 * n;

    float x1 = r_vec[(et0 >> 1) * 64 + 2 * c], y1 = r_vec[(et0 >> 1) * 64 + 2 * c + 1];
    n = rsqrtf(x1 * x1 + y1 * y1);
    float r0re = x1 * n, r0im = (et0 & 1) ? -y1 * n : y1 * n;

    float f0re = f1re * r0re - f1im * r0im;
    float f0im = f1re * r0im + f1im * r0re;

    float* base = g_fr + mp * (3 * HID);
    base[0 * HID + 2 * c] = f0re; base[0 * HID + 2 * c + 1] = f0im;
    base[1 * HID + 2 * c] = f1re; base[1 * HID + 2 * c + 1] = f1im;
    base[2 * HID + 2 * c] = 1.f;  base[2 * HID + 2 * c + 1] = 0.f;
}

// ---------------- feature towers: cp.async pipelined, f32x2 register-tiled ----------------
#define TOW_BM   128
#define XS_PITCH 68                       // floats; 272B row, 16B aligned, bank-shifted
#define XS_SZ    (TOW_BM * XS_PITCH)      // 8704 floats
#define WS_SZ    (64 * 64)                // 4096 floats
#define TOW_SMEM ((2 * XS_SZ + 2 * WS_SZ) * 4)   // 102400 B

__device__ __forceinline__ float gelu_exact(float z) {
    return 0.5f * z * (1.f + erff(z * 0.70710678118654752f));
}

__global__ void __launch_bounds__(256, 2) k_tower(
    const float* __restrict__ f0, const float* __restrict__ f1,
    const float* __restrict__ pw0, const float* __restrict__ pb0,
    const float* __restrict__ w20, const float* __restrict__ b20,
    const float* __restrict__ gm0, const float* __restrict__ be0,
    const float* __restrict__ pw1, const float* __restrict__ pb1,
    const float* __restrict__ w21, const float* __restrict__ b21,
    const float* __restrict__ gm1, const float* __restrict__ be1,
    const int* __restrict__ idx0, const int* __restrict__ idx1)
{
    int t = blockIdx.y;
    const float* feats = t ? f1  : f0;
    const float* pw    = t ? pw1 : pw0;
    const float* pb    = t ? pb1 : pb0;
    const float* w2    = t ? w21 : w20;
    const float* b2    = t ? b21 : b20;
    const float* gmw   = t ? gm1 : gm0;
    const float* bew   = t ? be1 : be0;
    const int*   idx   = t ? idx1 : idx0;

    extern __shared__ float sm[];
    float* xsp[2] = { sm, sm + XS_SZ };
    float* wsp[2] = { sm + 2 * XS_SZ, sm + 2 * XS_SZ + WS_SZ };
    unsigned smem_u32 = (unsigned)__cvta_generic_to_shared(sm);
    unsigned xsa[2] = { smem_u32, smem_u32 + XS_SZ * 4 };
    unsigned wsa[2] = { smem_u32 + 2 * XS_SZ * 4, smem_u32 + (2 * XS_SZ + WS_SZ) * 4 };

    int tid = threadIdx.x;
    int tx = tid & 15, ty = tid >> 4;
    int nb = blockIdx.x * TOW_BM;

    // prefetch issue lambda (chunk kc of GEMM1 into buffer b)
    auto prefetch = [&](int kc, int b) {
        #pragma unroll
        for (int r = 0; r < 8; ++r) {
            int i = tid + r * 256;
            int node = i >> 4, kq = i & 15;
            int ng = nb + node;
            cpa16(xsa[b] + (unsigned)(node * XS_PITCH + kq * 4) * 4,
                  feats + (size_t)ng * F0_DIM + kc + kq * 4, ng < N0_NODES);
        }
        #pragma unroll
        for (int r = 0; r < 4; ++r) {
            int i = tid + r * 256;
            int k = i >> 4, cq = i & 15;
            cpa16(wsa[b] + (unsigned)(k * 64 + cq * 4) * 4,
                  pw + (size_t)(kc + k) * HID + cq * 4, true);
        }
        CP_COMMIT();
    };

    float4 pbv = *(const float4*)(pb + tx * 4);
    ull acc[4][4];
    #pragma unroll
    for (int i = 0; i < 4; ++i) {
        acc[i][0] = pack2(pbv.x, pbv.x);
        acc[i][1] = pack2(pbv.y, pbv.y);
        acc[i][2] = pack2(pbv.z, pbv.z);
        acc[i][3] = pack2(pbv.w, pbv.w);
    }

    prefetch(0, 0);

    // ---- GEMM1: z = x @ pw + pb ----
    for (int c = 0; c < 8; ++c) {
        int b = c & 1;
        if (c < 7) { prefetch((c + 1) * 64, b ^ 1); CP_WAIT1(); }
        else       { CP_WAIT0(); }
        __syncthreads();

        const float* xs = xsp[b];
        const float* ws = wsp[b];
        #pragma unroll 4
        for (int k = 0; k < 64; ++k) {
            float4 wv = *(const float4*)(ws + k * 64 + tx * 4);
            ull w0 = pack2(wv.x, wv.x), w1 = pack2(wv.y, wv.y);
            ull w2p = pack2(wv.z, wv.z), w3 = pack2(wv.w, wv.w);
            #pragma unroll
            for (int i = 0; i < 4; ++i) {
                int row = ty * 8 + 2 * i;
                ull xv = pack2(xs[row * XS_PITCH + k], xs[(row + 1) * XS_PITCH + k]);
                ffma2(acc[i][0], xv, w0);
                ffma2(acc[i][1], xv, w1);
                ffma2(acc[i][2], xv, w2p);
                ffma2(acc[i][3], xv, w3);
            }
        }
        __syncthreads();
    }

    // ---- prefetch w2 into ws[0]; GELU -> xs[0] ----
    #pragma unroll
    for (int r = 0; r < 4; ++r) {
        int i = tid + r * 256;
        int k = i >> 4, cq = i & 15;
        cpa16(wsa[0] + (unsigned)(k * 64 + cq * 4) * 4, w2 + (size_t)k * HID + cq * 4, true);
    }
    CP_COMMIT();

    #pragma unroll
    for (int i = 0; i < 4; ++i)
        #pragma unroll
        for (int j = 0; j < 4; ++j) {
            float zl, zh;
            unpack2(acc[i][j], zl, zh);
            int row = ty * 8 + 2 * i, col = tx * 4 + j;
            xsp[0][row * XS_PITCH + col] = gelu_exact(zl);
            xsp[0][(row + 1) * XS_PITCH + col] = gelu_exact(zh);
        }
    CP_WAIT0();
    __syncthreads();

    // ---- GEMM2: y = h @ w2 + b2 + z ----
    float4 b2v = *(const float4*)(b2 + tx * 4);
    ull yacc[4][4];
    #pragma unroll
    for (int i = 0; i < 4; ++i) {
        yacc[i][0] = fadd2(acc[i][0], pack2(b2v.x, b2v.x));
        yacc[i][1] = fadd2(acc[i][1], pack2(b2v.y, b2v.y));
        yacc[i][2] = fadd2(acc[i][2], pack2(b2v.z, b2v.z));
        yacc[i][3] = fadd2(acc[i][3], pack2(b2v.w, b2v.w));
    }
    {
        const float* xs = xsp[0];
        const float* ws = wsp[0];
        #pragma unroll 4
        for (int k = 0; k < 64; ++k) {
            float4 wv = *(const float4*)(ws + k * 64 + tx * 4);
            ull w0 = pack2(wv.x, wv.x), w1 = pack2(wv.y, wv.y);
            ull w2p = pack2(wv.z, wv.z), w3 = pack2(wv.w, wv.w);
            #pragma unroll
            for (int i = 0; i < 4; ++i) {
                int row = ty * 8 + 2 * i;
                ull xv = pack2(xs[row * XS_PITCH + k], xs[(row + 1) * XS_PITCH + k]);
                ffma2(yacc[i][0], xv, w0);
                ffma2(yacc[i][1], xv, w1);
                ffma2(yacc[i][2], xv, w2p);
                ffma2(yacc[i][3], xv, w3);
            }
        }
    }

    // ---- LayerNorm (shuffle across 16 tx lanes) ----
    float y[8][4];
    #pragma unroll
    for (int i = 0; i < 4; ++i)
        #pragma unroll
        for (int j = 0; j < 4; ++j)
            unpack2(yacc[i][j], y[2 * i][j], y[2 * i + 1][j]);

    float4 gv = *(const float4*)(gmw + tx * 4);
    float4 bev = *(const float4*)(bew + tx * 4);

    #pragma unroll
    for (int i = 0; i < 8; ++i) {
        float s1 = y[i][0] + y[i][1] + y[i][2] + y[i][3];
        float s2 = y[i][0] * y[i][0] + y[i][1] * y[i][1] + y[i][2] * y[i][2] + y[i][3] * y[i][3];
        #pragma unroll
        for (int o = 8; o > 0; o >>= 1) {
            s1 += __shfl_xor_sync(0xffffffffu, s1, o);
            s2 += __shfl_xor_sync(0xffffffffu, s2, o);
        }
        float mu  = s1 * (1.f / 64.f);
        float var = s2 * (1.f / 64.f) - mu * mu;
        float rs  = rsqrtf(var + 1e-5f);
        int ng = nb + ty * 8 + i;
        if (ng < N0_NODES) {
            int dst = idx[ng];
            float4 o4;
            o4.x = (y[i][0] - mu) * rs * gv.x + bev.x;
            o4.y = (y[i][1] - mu) * rs * gv.y + bev.y;
            o4.z = (y[i][2] - mu) * rs * gv.z + bev.z;
            o4.w = (y[i][3] - mu) * rs * gv.w + bev.w;
            *(float4*)(g_feat + (size_t)dst * HID + tx * 4) = o4;
        }
    }
}

// ---------------- metapath gather + edge softmax accumulate (v4 red) ----------------
__global__ void k_metapath(
    const int* __restrict__ emi_u, const int* __restrict__ tgt_u,
    const int* __restrict__ emi_i, const int* __restrict__ tgt_i,
    const float* __restrict__ attn_u, const float* __restrict__ attn_i)
{
    int mp = blockIdx.y;
    const int*   emi  = (mp < 2 ? emi_u : emi_i) + (size_t)(mp & 1) * E_CNT * 3;
    const int*   tgt  = (mp < 2 ? tgt_u : tgt_i) + (size_t)(mp & 1) * E_CNT;
    const float* attn = (mp < 2 ? attn_u : attn_i) + (mp & 1) * HID;

    int tid  = threadIdx.x;
    int sub  = tid & 15;
    int inst = blockIdx.x * (blockDim.x >> 4) + (tid >> 4);

    const float4* fr4 = (const float4*)g_fr + mp * 48;
    float4 fr0 = fr4[sub], fr1 = fr4[16 + sub], fr2 = fr4[32 + sub];
    float4 av = ((const float4*)attn)[sub];

    int n0 = __ldg(emi + inst * 3);
    int n1 = __ldg(emi + inst * 3 + 1);
    int n2 = __ldg(emi + inst * 3 + 2);
    int t  = __ldg(tgt + inst);

    const float4* feat4 = (const float4*)g_feat;
    float4 v0 = __ldg(feat4 + (size_t)n0 * 16 + sub);
    float4 v1 = __ldg(feat4 + (size_t)n1 * 16 + sub);
    float4 v2 = __ldg(feat4 + (size_t)n2 * 16 + sub);

    float hx = (v0.x * fr0.x - v0.y * fr0.y) + (v1.x * fr1.x - v1.y * fr1.y) + (v2.x * fr2.x - v2.y * fr2.y);
    float hy = (v0.x * fr0.y + v0.y * fr0.x) + (v1.x * fr1.y + v1.y * fr1.x) + (v2.x * fr2.y + v2.y * fr2.x);
    float hz = (v0.z * fr0.z - v0.w * fr0.w) + (v1.z * fr1.z - v1.w * fr1.w) + (v2.z * fr2.z - v2.w * fr2.w);
    float hw = (v0.z * fr0.w + v0.w * fr0.z) + (v1.z * fr1.w + v1.w * fr1.z) + (v2.z * fr2.w + v2.w * fr2.z);
    const float inv3 = (1.f / 3.f);
    hx *= inv3; hy *= inv3; hz *= inv3; hw *= inv3;

    float p = hx * av.x + hy * av.y + hz * av.z + hw * av.w;
    p += __shfl_xor_sync(0xffffffffu, p, 1);
    float e = p > 0.f ? p : 0.01f * p;
    float a = expf(e);

    size_t base = (size_t)mp * BATCH + t;
    if (!(sub & 1)) atomicAdd(&g_s[base * NHEAD + (sub >> 1)], a);
    float* rb = g_ret + base * HID + sub * 4;
    asm volatile("red.global.add.v4.f32 [%0], {%1, %2, %3, %4};"
                 :: "l"(rb), "f"(a * hx), "f"(a * hy), "f"(a * hz), "f"(a * hw)
                 : "memory");
}

// ---------------- normalize + elu + semantic scores (batched, w1 cached) ----------------
#define NS_BB 16
__global__ void __launch_bounds__(128) k_norm_sem(
    const float* __restrict__ su_w1, const float* __restrict__ su_b1, const float* __restrict__ su_w2,
    const float* __restrict__ si_w1, const float* __restrict__ si_b1, const float* __restrict__ si_w2)
{
    int mp = blockIdx.y, tid = threadIdx.x;
    __shared__ float w1s[HID * AV_DIM];
    __shared__ float sh[HID];
    __shared__ float red[4];

    const float* w1 = (mp < 2) ? su_w1 : si_w1;
    const float* b1 = (mp < 2) ? su_b1 : si_b1;
    const float* w2 = (mp < 2) ? su_w2 : si_w2;

    for (int i = tid; i < HID * AV_DIM; i += 128) w1s[i] = w1[i];
    float b1v = b1[tid], w2v = w2[tid];
    __syncthreads();

    float local = 0.f;
    for (int bb = 0; bb < NS_BB; ++bb) {
        int b = blockIdx.x * NS_BB + bb;
        size_t base = ((size_t)mp * BATCH + b) * HID;
        if (tid < HID) {
            float sv = g_s[((size_t)mp * BATCH + b) * NHEAD + (tid >> 3)];
            float v = g_ret[base + tid] / (sv + 1e-9f);
            v = v > 0.f ? v : expf(v) - 1.f;
            g_mpout[base + tid] = v;
            sh[tid] = v;
        }
        __syncthreads();

        float acc = b1v;
        #pragma unroll
        for (int k = 0; k < HID; ++k) acc += sh[k] * w1s[k * AV_DIM + tid];
        float v = tanhf(acc) * w2v;
        #pragma unroll
        for (int o = 16; o > 0; o >>= 1) v += __shfl_xor_sync(0xffffffffu, v, o);
        if ((tid & 31) == 0) red[tid >> 5] = v;
        __syncthreads();
        if (tid == 0) local += red[0] + red[1] + red[2] + red[3];
        __syncthreads();
    }
    if (tid == 0) atomicAdd(&g_sem[mp], local);
}

// ---------------- semantic fusion + product MLP + softmax (batched) ----------------
#define KF_BB 16
__global__ void __launch_bounds__(128) k_final(
    const float* __restrict__ cw1, const float* __restrict__ cb1,
    const float* __restrict__ cw2, float* __restrict__ out)
{
    int tid = threadIdx.x;
    __shared__ float cw1s[HID * CH_DIM];
    __shared__ float xsb[HID];
    __shared__ float r0s[4], r1s[4];

    for (int i = tid; i < HID * CH_DIM; i += 128) cw1s[i] = cw1[i];
    float cb1v = cb1[tid];
    float cw20 = cw2[tid * 2], cw21 = cw2[tid * 2 + 1];

    float s0 = g_sem[0] * (1.f / BATCH), s1 = g_sem[1] * (1.f / BATCH);
    float s2 = g_sem[2] * (1.f / BATCH), s3 = g_sem[3] * (1.f / BATCH);
    float mU = fmaxf(s0, s1), mI = fmaxf(s2, s3);
    float e0 = expf(s0 - mU), e1 = expf(s1 - mU);
    float e2 = expf(s2 - mI), e3 = expf(s3 - mI);
    float bu0 = e0 / (e0 + e1), bu1 = e1 / (e0 + e1);
    float bi0 = e2 / (e2 + e3), bi1 = e3 / (e2 + e3);
    __syncthreads();

    for (int bb = 0; bb < KF_BB; ++bb) {
        int b = blockIdx.x * KF_BB + bb;
        if (tid < HID) {
            float hu = bu0 * g_mpout[((size_t)0 * BATCH + b) * HID + tid]
                     + bu1 * g_mpout[((size_t)1 * BATCH + b) * HID + tid];
            float hi = bi0 * g_mpout[((size_t)2 * BATCH + b) * HID + tid]
                     + bi1 * g_mpout[((size_t)3 * BATCH + b) * HID + tid];
            xsb[tid] = hu * hi;
        }
        __syncthreads();

        float acc = cb1v;
        #pragma unroll
        for (int k = 0; k < HID; ++k) acc += xsb[k] * cw1s[k * CH_DIM + tid];
        acc = fmaxf(acc, 0.f);
        float v0 = acc * cw20, v1 = acc * cw21;
        #pragma unroll
        for (int o = 16; o > 0; o >>= 1) {
            v0 += __shfl_xor_sync(0xffffffffu, v0, o);
            v1 += __shfl_xor_sync(0xffffffffu, v1, o);
        }
        if ((tid & 31) == 0) { r0s[tid >> 5] = v0; r1s[tid >> 5] = v1; }
        __syncthreads();
        if (tid == 0) {
            float l0 = r0s[0] + r0s[1] + r0s[2] + r0s[3];
            float l1 = r1s[0] + r1s[1] + r1s[2] + r1s[3];
            float m = fmaxf(l0, l1);
            float a0 = expf(l0 - m), a1 = expf(l1 - m);
            float inv = 1.f / (a0 + a1);
            out[b * 2 + 0] = a0 * inv;
            out[b * 2 + 1] = a1 * inv;
        }
        __syncthreads();
    }
}

// ---------------- launch ----------------
extern "C" void kernel_launch(void* const* d_in, const int* in_sizes, int n_in,
                              void* d_out, int out_size) {
    (void)in_sizes; (void)n_in; (void)out_size;
    const float* feats0 = (const float*)d_in[0];
    const float* feats1 = (const float*)d_in[1];
    const float* t0_pw = (const float*)d_in[2];
    const float* t0_pb = (const float*)d_in[3];
    const float* t0_w2 = (const float*)d_in[4];
    const float* t0_b2 = (const float*)d_in[5];
    const float* t0_g  = (const float*)d_in[6];
    const float* t0_be = (const float*)d_in[7];
    const float* t1_pw = (const float*)d_in[8];
    const float* t1_pb = (const float*)d_in[9];
    const float* t1_w2 = (const float*)d_in[10];
    const float* t1_b2 = (const float*)d_in[11];
    const float* t1_g  = (const float*)d_in[12];
    const float* t1_be = (const float*)d_in[13];
    const float* r_vec = (const float*)d_in[14];
    const float* attn_user = (const float*)d_in[15];
    const float* attn_item = (const float*)d_in[16];
    const float* su_w1 = (const float*)d_in[17];
    const float* su_b1 = (const float*)d_in[18];
    const float* su_w2 = (const float*)d_in[19];
    const float* si_w1 = (const float*)d_in[20];
    const float* si_b1 = (const float*)d_in[21];
    const float* si_w2 = (const float*)d_in[22];
    const float* cw1   = (const float*)d_in[23];
    const float* cb1   = (const float*)d_in[24];
    const float* cw2   = (const float*)d_in[25];
    const int* idx0 = (const int*)d_in[26];
    const int* idx1 = (const int*)d_in[27];
    const int* emi_user = (const int*)d_in[28];
    const int* tgt_user = (const int*)d_in[29];
    const int* emi_item = (const int*)d_in[30];
    const int* tgt_item = (const int*)d_in[31];
    float* out = (float*)d_out;

    cudaFuncSetAttribute(k_tower, cudaFuncAttributeMaxDynamicSharedMemorySize, TOW_SMEM);

    // zero accumulators via memset nodes
    void* p_s; void* p_ret; void* p_sem;
    cudaGetSymbolAddress(&p_s, g_s);
    cudaGetSymbolAddress(&p_ret, g_ret);
    cudaGetSymbolAddress(&p_sem, g_sem);
    cudaMemsetAsync(p_s, 0, 4 * BATCH * NHEAD * sizeof(float), 0);
    cudaMemsetAsync(p_ret, 0, (size_t)4 * BATCH * HID * sizeof(float), 0);
    cudaMemsetAsync(p_sem, 0, 4 * sizeof(float), 0);

    k_fr<<<1, 128>>>(r_vec);

    dim3 tg((N0_NODES + TOW_BM - 1) / TOW_BM, 2);
    k_tower<<<tg, 256, TOW_SMEM>>>(feats0, feats1,
        t0_pw, t0_pb, t0_w2, t0_b2, t0_g, t0_be,
        t1_pw, t1_pb, t1_w2, t1_b2, t1_g, t1_be,
        idx0, idx1);

    dim3 mg(E_CNT / 16, 4);
    k_metapath<<<mg, 256>>>(emi_user, tgt_user, emi_item, tgt_item, attn_user, attn_item);

    dim3 ng(BATCH / NS_BB, 4);
    k_norm_sem<<<ng, 128>>>(su_w1, su_b1, su_w2, si_w1, si_b1, si_w2);

    k_final<<<BATCH / KF_BB, 128>>>(cw1, cb1, cw2, out);
}

// round 7
// speedup vs baseline: 1.0518x; 1.0518x over previous
#include <cuda_runtime.h>
#include <cuda_bf16.h>
#include <math.h>

// ---------------- problem constants ----------------
#define N0_NODES 20000
#define N_ALL    40000
#define F0_DIM   512
#define HID      64
#define NHEAD    8
#define E_CNT    200000
#define BATCH    8192
#define AV_DIM   128
#define CH_DIM   128

typedef unsigned long long ull;

__device__ __forceinline__ ull pack2(float lo, float hi) {
    ull r; asm("mov.b64 %0, {%1, %2};" : "=l"(r) : "f"(lo), "f"(hi)); return r;
}
__device__ __forceinline__ void unpack2(ull v, float& lo, float& hi) {
    asm("mov.b64 {%0, %1}, %2;" : "=f"(lo), "=f"(hi) : "l"(v));
}
__device__ __forceinline__ void ffma2(ull& d, ull a, ull b) {
    asm("fma.rn.f32x2 %0, %1, %2, %0;" : "+l"(d) : "l"(a), "l"(b));
}
__device__ __forceinline__ ull fadd2(ull a, ull b) {
    ull r; asm("add.rn.f32x2 %0, %1, %2;" : "=l"(r) : "l"(a), "l"(b)); return r;
}
__device__ __forceinline__ float tanh_fast(float x) {
    float y; asm("tanh.approx.f32 %0, %1;" : "=f"(y) : "f"(x)); return y;
}
__device__ __forceinline__ void cpa16(unsigned dst, const float* src, bool valid) {
    int sz = valid ? 16 : 0;
    asm volatile("cp.async.cg.shared.global [%0], [%1], 16, %2;" :: "r"(dst), "l"(src), "r"(sz));
}
#define CP_COMMIT() asm volatile("cp.async.commit_group;")
#define CP_WAIT1()  asm volatile("cp.async.wait_group 1;")
#define CP_WAIT0()  asm volatile("cp.async.wait_group 0;")

// ---------------- device scratch ----------------
__device__ __align__(16) float g_feat[N_ALL * HID];
__device__ __align__(16) float g_fr[4 * 3 * HID];
__device__ __align__(16) float g_s[4 * BATCH * NHEAD];
__device__ __align__(16) float g_ret[4 * BATCH * HID];
__device__ __align__(16) float g_mpout[4 * BATCH * HID];
__device__ __align__(16) float g_sem[4];

// ---------------- rotation precompute ----------------
__global__ void k_fr(const float* __restrict__ r_vec) {
    int tid = threadIdx.x;
    if (tid >= 128) return;
    int mp = tid >> 5, c = tid & 31;
    int et0 = (mp < 2) ? 0 : 1;
    int et1 = (mp < 2) ? 1 : 0;

    float x0 = r_vec[(et1 >> 1) * 64 + 2 * c], y0 = r_vec[(et1 >> 1) * 64 + 2 * c + 1];
    float n = rsqrtf(x0 * x0 + y0 * y0);
    float f1re = x0 * n, f1im = (et1 & 1) ? -y0 * n : y0 * n;

    float x1 = r_vec[(et0 >> 1) * 64 + 2 * c], y1 = r_vec[(et0 >> 1) * 64 + 2 * c + 1];
    n = rsqrtf(x1 * x1 + y1 * y1);
    float r0re = x1 * n, r0im = (et0 & 1) ? -y1 * n : y1 * n;

    float f0re = f1re * r0re - f1im * r0im;
    float f0im = f1re * r0im + f1im * r0re;

    float* base = g_fr + mp * (3 * HID);
    base[0 * HID + 2 * c] = f0re; base[0 * HID + 2 * c + 1] = f0im;
    base[1 * HID + 2 * c] = f1re; base[1 * HID + 2 * c + 1] = f1im;
    base[2 * HID + 2 * c] = 1.f;  base[2 * HID + 2 * c + 1] = 0.f;
}

// ---------------- feature towers: cp.async pipelined, f32x2 register-tiled ----------------
#define TOW_BM   128
#define XS_PITCH 68
#define XS_SZ    (TOW_BM * XS_PITCH)
#define WS_SZ    (64 * 64)
#define TOW_SMEM ((2 * XS_SZ + 2 * WS_SZ) * 4)

__device__ __forceinline__ float gelu_exact(float z) {
    return 0.5f * z * (1.f + erff(z * 0.70710678118654752f));
}

__global__ void __launch_bounds__(256, 2) k_tower(
    const float* __restrict__ f0, const float* __restrict__ f1,
    const float* __restrict__ pw0, const float* __restrict__ pb0,
    const float* __restrict__ w20, const float* __restrict__ b20,
    const float* __restrict__ gm0, const float* __restrict__ be0,
    const float* __restrict__ pw1, const float* __restrict__ pb1,
    const float* __restrict__ w21, const float* __restrict__ b21,
    const float* __restrict__ gm1, const float* __restrict__ be1,
    const int* __restrict__ idx0, const int* __restrict__ idx1)
{
    int t = blockIdx.y;
    const float* feats = t ? f1  : f0;
    const float* pw    = t ? pw1 : pw0;
    const float* pb    = t ? pb1 : pb0;
    const float* w2    = t ? w21 : w20;
    const float* b2    = t ? b21 : b20;
    const float* gmw   = t ? gm1 : gm0;
    const float* bew   = t ? be1 : be0;
    const int*   idx   = t ? idx1 : idx0;

    extern __shared__ float sm[];
    float* xsp[2] = { sm, sm + XS_SZ };
    float* wsp[2] = { sm + 2 * XS_SZ, sm + 2 * XS_SZ + WS_SZ };
    unsigned smem_u32 = (unsigned)__cvta_generic_to_shared(sm);
    unsigned xsa[2] = { smem_u32, smem_u32 + XS_SZ * 4 };
    unsigned wsa[2] = { smem_u32 + 2 * XS_SZ * 4, smem_u32 + (2 * XS_SZ + WS_SZ) * 4 };

    int tid = threadIdx.x;
    int tx = tid & 15, ty = tid >> 4;
    int nb = blockIdx.x * TOW_BM;

    auto prefetch = [&](int kc, int b) {
        #pragma unroll
        for (int r = 0; r < 8; ++r) {
            int i = tid + r * 256;
            int node = i >> 4, kq = i & 15;
            int ng = nb + node;
            cpa16(xsa[b] + (unsigned)(node * XS_PITCH + kq * 4) * 4,
                  feats + (size_t)ng * F0_DIM + kc + kq * 4, ng < N0_NODES);
        }
        #pragma unroll
        for (int r = 0; r < 4; ++r) {
            int i = tid + r * 256;
            int k = i >> 4, cq = i & 15;
            cpa16(wsa[b] + (unsigned)(k * 64 + cq * 4) * 4,
                  pw + (size_t)(kc + k) * HID + cq * 4, true);
        }
        CP_COMMIT();
    };

    float4 pbv = *(const float4*)(pb + tx * 4);
    ull acc[4][4];
    #pragma unroll
    for (int i = 0; i < 4; ++i) {
        acc[i][0] = pack2(pbv.x, pbv.x);
        acc[i][1] = pack2(pbv.y, pbv.y);
        acc[i][2] = pack2(pbv.z, pbv.z);
        acc[i][3] = pack2(pbv.w, pbv.w);
    }

    prefetch(0, 0);

    for (int c = 0; c < 8; ++c) {
        int b = c & 1;
        if (c < 7) { prefetch((c + 1) * 64, b ^ 1); CP_WAIT1(); }
        else       { CP_WAIT0(); }
        __syncthreads();

        const float* xs = xsp[b];
        const float* ws = wsp[b];
        #pragma unroll 4
        for (int k = 0; k < 64; ++k) {
            float4 wv = *(const float4*)(ws + k * 64 + tx * 4);
            ull w0 = pack2(wv.x, wv.x), w1 = pack2(wv.y, wv.y);
            ull w2p = pack2(wv.z, wv.z), w3 = pack2(wv.w, wv.w);
            #pragma unroll
            for (int i = 0; i < 4; ++i) {
                int row = ty * 8 + 2 * i;
                ull xv = pack2(xs[row * XS_PITCH + k], xs[(row + 1) * XS_PITCH + k]);
                ffma2(acc[i][0], xv, w0);
                ffma2(acc[i][1], xv, w1);
                ffma2(acc[i][2], xv, w2p);
                ffma2(acc[i][3], xv, w3);
            }
        }
        __syncthreads();
    }

    #pragma unroll
    for (int r = 0; r < 4; ++r) {
        int i = tid + r * 256;
        int k = i >> 4, cq = i & 15;
        cpa16(wsa[0] + (unsigned)(k * 64 + cq * 4) * 4, w2 + (size_t)k * HID + cq * 4, true);
    }
    CP_COMMIT();

    #pragma unroll
    for (int i = 0; i < 4; ++i)
        #pragma unroll
        for (int j = 0; j < 4; ++j) {
            float zl, zh;
            unpack2(acc[i][j], zl, zh);
            int row = ty * 8 + 2 * i, col = tx * 4 + j;
            xsp[0][row * XS_PITCH + col] = gelu_exact(zl);
            xsp[0][(row + 1) * XS_PITCH + col] = gelu_exact(zh);
        }
    CP_WAIT0();
    __syncthreads();

    float4 b2v = *(const float4*)(b2 + tx * 4);
    ull yacc[4][4];
    #pragma unroll
    for (int i = 0; i < 4; ++i) {
        yacc[i][0] = fadd2(acc[i][0], pack2(b2v.x, b2v.x));
        yacc[i][1] = fadd2(acc[i][1], pack2(b2v.y, b2v.y));
        yacc[i][2] = fadd2(acc[i][2], pack2(b2v.z, b2v.z));
        yacc[i][3] = fadd2(acc[i][3], pack2(b2v.w, b2v.w));
    }
    {
        const float* xs = xsp[0];
        const float* ws = wsp[0];
        #pragma unroll 4
        for (int k = 0; k < 64; ++k) {
            float4 wv = *(const float4*)(ws + k * 64 + tx * 4);
            ull w0 = pack2(wv.x, wv.x), w1 = pack2(wv.y, wv.y);
            ull w2p = pack2(wv.z, wv.z), w3 = pack2(wv.w, wv.w);
            #pragma unroll
            for (int i = 0; i < 4; ++i) {
                int row = ty * 8 + 2 * i;
                ull xv = pack2(xs[row * XS_PITCH + k], xs[(row + 1) * XS_PITCH + k]);
                ffma2(yacc[i][0], xv, w0);
                ffma2(yacc[i][1], xv, w1);
                ffma2(yacc[i][2], xv, w2p);
                ffma2(yacc[i][3], xv, w3);
            }
        }
    }

    float y[8][4];
    #pragma unroll
    for (int i = 0; i < 4; ++i)
        #pragma unroll
        for (int j = 0; j < 4; ++j)
            unpack2(yacc[i][j], y[2 * i][j], y[2 * i + 1][j]);

    float4 gv = *(const float4*)(gmw + tx * 4);
    float4 bev = *(const float4*)(bew + tx * 4);

    #pragma unroll
    for (int i = 0; i < 8; ++i) {
        float s1 = y[i][0] + y[i][1] + y[i][2] + y[i][3];
        float s2 = y[i][0] * y[i][0] + y[i][1] * y[i][1] + y[i][2] * y[i][2] + y[i][3] * y[i][3];
        #pragma unroll
        for (int o = 8; o > 0; o >>= 1) {
            s1 += __shfl_xor_sync(0xffffffffu, s1, o);
            s2 += __shfl_xor_sync(0xffffffffu, s2, o);
        }
        float mu  = s1 * (1.f / 64.f);
        float var = s2 * (1.f / 64.f) - mu * mu;
        float rs  = rsqrtf(var + 1e-5f);
        int ng = nb + ty * 8 + i;
        if (ng < N0_NODES) {
            int dst = idx[ng];
            float4 o4;
            o4.x = (y[i][0] - mu) * rs * gv.x + bev.x;
            o4.y = (y[i][1] - mu) * rs * gv.y + bev.y;
            o4.z = (y[i][2] - mu) * rs * gv.z + bev.z;
            o4.w = (y[i][3] - mu) * rs * gv.w + bev.w;
            *(float4*)(g_feat + (size_t)dst * HID + tx * 4) = o4;
        }
    }
}

// ---------------- metapath gather + edge softmax accumulate (v4 red) ----------------
__global__ void k_metapath(
    const int* __restrict__ emi_u, const int* __restrict__ tgt_u,
    const int* __restrict__ emi_i, const int* __restrict__ tgt_i,
    const float* __restrict__ attn_u, const float* __restrict__ attn_i)
{
    int mp = blockIdx.y;
    const int*   emi  = (mp < 2 ? emi_u : emi_i) + (size_t)(mp & 1) * E_CNT * 3;
    const int*   tgt  = (mp < 2 ? tgt_u : tgt_i) + (size_t)(mp & 1) * E_CNT;
    const float* attn = (mp < 2 ? attn_u : attn_i) + (mp & 1) * HID;

    int tid  = threadIdx.x;
    int sub  = tid & 15;
    int inst = blockIdx.x * (blockDim.x >> 4) + (tid >> 4);

    const float4* fr4 = (const float4*)g_fr + mp * 48;
    float4 fr0 = fr4[sub], fr1 = fr4[16 + sub], fr2 = fr4[32 + sub];
    float4 av = ((const float4*)attn)[sub];

    int n0 = __ldg(emi + inst * 3);
    int n1 = __ldg(emi + inst * 3 + 1);
    int n2 = __ldg(emi + inst * 3 + 2);
    int t  = __ldg(tgt + inst);

    const float4* feat4 = (const float4*)g_feat;
    float4 v0 = __ldg(feat4 + (size_t)n0 * 16 + sub);
    float4 v1 = __ldg(feat4 + (size_t)n1 * 16 + sub);
    float4 v2 = __ldg(feat4 + (size_t)n2 * 16 + sub);

    float hx = (v0.x * fr0.x - v0.y * fr0.y) + (v1.x * fr1.x - v1.y * fr1.y) + (v2.x * fr2.x - v2.y * fr2.y);
    float hy = (v0.x * fr0.y + v0.y * fr0.x) + (v1.x * fr1.y + v1.y * fr1.x) + (v2.x * fr2.y + v2.y * fr2.x);
    float hz = (v0.z * fr0.z - v0.w * fr0.w) + (v1.z * fr1.z - v1.w * fr1.w) + (v2.z * fr2.z - v2.w * fr2.w);
    float hw = (v0.z * fr0.w + v0.w * fr0.z) + (v1.z * fr1.w + v1.w * fr1.z) + (v2.z * fr2.w + v2.w * fr2.z);
    const float inv3 = (1.f / 3.f);
    hx *= inv3; hy *= inv3; hz *= inv3; hw *= inv3;

    float p = hx * av.x + hy * av.y + hz * av.z + hw * av.w;
    p += __shfl_xor_sync(0xffffffffu, p, 1);
    float e = p > 0.f ? p : 0.01f * p;
    float a = expf(e);

    size_t base = (size_t)mp * BATCH + t;
    if (!(sub & 1)) atomicAdd(&g_s[base * NHEAD + (sub >> 1)], a);
    float* rb = g_ret + base * HID + sub * 4;
    asm volatile("red.global.add.v4.f32 [%0], {%1, %2, %3, %4};"
                 :: "l"(rb), "f"(a * hx), "f"(a * hy), "f"(a * hz), "f"(a * hw)
                 : "memory");
}

// ---------------- fused normalize+elu+mpout + semantic GEMV ----------------
// grid (BATCH/128, 4) ; block 256. Each block: 128 b rows of one mp.
// Thread: bl = tid&127, chalf = tid>>7 owns 64 of 128 attn cols.
#define NSEM_BB 128
#define NSEM_SMEM ((HID * AV_DIM + HID * NSEM_BB) * 4)   // 32KB + 32KB
__global__ void __launch_bounds__(256) k_normsem(
    const float* __restrict__ su_w1, const float* __restrict__ su_b1, const float* __restrict__ su_w2,
    const float* __restrict__ si_w1, const float* __restrict__ si_b1, const float* __restrict__ si_w2)
{
    int mp = blockIdx.y, tid = threadIdx.x;
    extern __shared__ float dsm[];
    float* w1s = dsm;                  // [k][c] 64x128
    float* hs  = dsm + HID * AV_DIM;   // [k][bl] 64x128
    __shared__ float rbuf[8];

    const float* w1 = (mp < 2) ? su_w1 : si_w1;
    const float* b1 = (mp < 2) ? su_b1 : si_b1;
    const float* w2 = (mp < 2) ? su_w2 : si_w2;

    for (int i = tid; i < HID * AV_DIM; i += 256) w1s[i] = w1[i];

    int b0 = blockIdx.x * NSEM_BB;
    // phase 1: v = elu(ret/s), write mpout, stage transposed into hs
    for (int i = tid; i < NSEM_BB * HID; i += 256) {
        int bl = i >> 6, k = i & 63;
        size_t row = (size_t)mp * BATCH + b0 + bl;
        float sv = g_s[row * NHEAD + (k >> 3)];
        float v = g_ret[row * HID + k] / (sv + 1e-9f);
        v = v > 0.f ? v : expf(v) - 1.f;
        g_mpout[row * HID + k] = v;
        hs[k * NSEM_BB + bl] = v;
    }
    __syncthreads();

    // phase 2: semantic GEMV, thread owns (bl, 64 cols)
    int bl = tid & 127, ch = tid >> 7;
    int c0 = ch * 64;
    float ssum = 0.f;
    #pragma unroll 4
    for (int cc = 0; cc < 64; cc += 4) {
        int c = c0 + cc;
        float4 bv = *(const float4*)(b1 + c);
        float a0 = bv.x, a1 = bv.y, a2 = bv.z, a3 = bv.w;
        #pragma unroll 8
        for (int k = 0; k < HID; ++k) {
            float xv = hs[k * NSEM_BB + bl];
            float4 wv = *(const float4*)(w1s + k * AV_DIM + c);
            a0 = fmaf(xv, wv.x, a0);
            a1 = fmaf(xv, wv.y, a1);
            a2 = fmaf(xv, wv.z, a2);
            a3 = fmaf(xv, wv.w, a3);
        }
        float4 w2v = *(const float4*)(w2 + c);
        ssum += tanh_fast(a0) * w2v.x + tanh_fast(a1) * w2v.y
              + tanh_fast(a2) * w2v.z + tanh_fast(a3) * w2v.w;
    }
    #pragma unroll
    for (int o = 16; o > 0; o >>= 1) ssum += __shfl_xor_sync(0xffffffffu, ssum, o);
    if ((tid & 31) == 0) rbuf[tid >> 5] = ssum;
    __syncthreads();
    if (tid == 0) {
        float t = rbuf[0] + rbuf[1] + rbuf[2] + rbuf[3] + rbuf[4] + rbuf[5] + rbuf[6] + rbuf[7];
        atomicAdd(&g_sem[mp], t);
    }
}

// ---------------- semantic fusion + product MLP + softmax ----------------
// grid BATCH/64 ; block 128. Each block 64 b. Thread: bl = tid&63, ch = tid>>6.
#define KF_BB 64
#define KF_SMEM ((HID * CH_DIM + HID * KF_BB + 2 * KF_BB) * 4)
__global__ void __launch_bounds__(128) k_final(
    const float* __restrict__ cw1, const float* __restrict__ cb1,
    const float* __restrict__ cw2, float* __restrict__ out)
{
    int tid = threadIdx.x;
    extern __shared__ float dsm[];
    float* cw1s = dsm;                     // [k][c] 64x128
    float* xs   = dsm + HID * CH_DIM;      // [k][bl] 64x64
    float* pl0  = xs + HID * KF_BB;        // [64]
    float* pl1  = pl0 + KF_BB;             // [64]

    for (int i = tid; i < HID * CH_DIM; i += 128) cw1s[i] = cw1[i];

    float s0 = g_sem[0] * (1.f / BATCH), s1 = g_sem[1] * (1.f / BATCH);
    float s2 = g_sem[2] * (1.f / BATCH), s3 = g_sem[3] * (1.f / BATCH);
    float mU = fmaxf(s0, s1), mI = fmaxf(s2, s3);
    float e0 = expf(s0 - mU), e1 = expf(s1 - mU);
    float e2 = expf(s2 - mI), e3 = expf(s3 - mI);
    float bu0 = e0 / (e0 + e1), bu1 = e1 / (e0 + e1);
    float bi0 = e2 / (e2 + e3), bi1 = e3 / (e2 + e3);

    int b0 = blockIdx.x * KF_BB;
    for (int i = tid; i < KF_BB * HID; i += 128) {
        int bl = i >> 6, k = i & 63;
        size_t b = b0 + bl;
        float hu = bu0 * g_mpout[((size_t)0 * BATCH + b) * HID + k]
                 + bu1 * g_mpout[((size_t)1 * BATCH + b) * HID + k];
        float hi = bi0 * g_mpout[((size_t)2 * BATCH + b) * HID + k]
                 + bi1 * g_mpout[((size_t)3 * BATCH + b) * HID + k];
        xs[k * KF_BB + bl] = hu * hi;
    }
    __syncthreads();

    int bl = tid & 63, ch = tid >> 6;
    int c0 = ch * 64;
    float l0 = 0.f, l1 = 0.f;
    #pragma unroll 4
    for (int cc = 0; cc < 64; cc += 4) {
        int c = c0 + cc;
        float4 bv = *(const float4*)(cb1 + c);
        float a0 = bv.x, a1 = bv.y, a2 = bv.z, a3 = bv.w;
        #pragma unroll 8
        for (int k = 0; k < HID; ++k) {
            float xv = xs[k * KF_BB + bl];
            float4 wv = *(const float4*)(cw1s + k * CH_DIM + c);
            a0 = fmaf(xv, wv.x, a0);
            a1 = fmaf(xv, wv.y, a1);
            a2 = fmaf(xv, wv.z, a2);
            a3 = fmaf(xv, wv.w, a3);
        }
        a0 = fmaxf(a0, 0.f); a1 = fmaxf(a1, 0.f);
        a2 = fmaxf(a2, 0.f); a3 = fmaxf(a3, 0.f);
        float4 wa = *(const float4*)(cw2 + 2 * c);       // c,c+1 pairs
        float4 wb = *(const float4*)(cw2 + 2 * c + 4);   // c+2,c+3 pairs
        l0 += a0 * wa.x + a1 * wa.z + a2 * wb.x + a3 * wb.z;
        l1 += a0 * wa.y + a1 * wa.w + a2 * wb.y + a3 * wb.w;
    }
    if (ch == 1) { pl0[bl] = l0; pl1[bl] = l1; }
    __syncthreads();
    if (ch == 0) {
        l0 += pl0[bl]; l1 += pl1[bl];
        float m = fmaxf(l0, l1);
        float a0 = expf(l0 - m), a1 = expf(l1 - m);
        float inv = 1.f / (a0 + a1);
        out[(b0 + bl) * 2 + 0] = a0 * inv;
        out[(b0 + bl) * 2 + 1] = a1 * inv;
    }
}

// ---------------- launch ----------------
extern "C" void kernel_launch(void* const* d_in, const int* in_sizes, int n_in,
                              void* d_out, int out_size) {
    (void)in_sizes; (void)n_in; (void)out_size;
    const float* feats0 = (const float*)d_in[0];
    const float* feats1 = (const float*)d_in[1];
    const float* t0_pw = (const float*)d_in[2];
    const float* t0_pb = (const float*)d_in[3];
    const float* t0_w2 = (const float*)d_in[4];
    const float* t0_b2 = (const float*)d_in[5];
    const float* t0_g  = (const float*)d_in[6];
    const float* t0_be = (const float*)d_in[7];
    const float* t1_pw = (const float*)d_in[8];
    const float* t1_pb = (const float*)d_in[9];
    const float* t1_w2 = (const float*)d_in[10];
    const float* t1_b2 = (const float*)d_in[11];
    const float* t1_g  = (const float*)d_in[12];
    const float* t1_be = (const float*)d_in[13];
    const float* r_vec = (const float*)d_in[14];
    const float* attn_user = (const float*)d_in[15];
    const float* attn_item = (const float*)d_in[16];
    const float* su_w1 = (const float*)d_in[17];
    const float* su_b1 = (const float*)d_in[18];
    const float* su_w2 = (const float*)d_in[19];
    const float* si_w1 = (const float*)d_in[20];
    const float* si_b1 = (const float*)d_in[21];
    const float* si_w2 = (const float*)d_in[22];
    const float* cw1   = (const float*)d_in[23];
    const float* cb1   = (const float*)d_in[24];
    const float* cw2   = (const float*)d_in[25];
    const int* idx0 = (const int*)d_in[26];
    const int* idx1 = (const int*)d_in[27];
    const int* emi_user = (const int*)d_in[28];
    const int* tgt_user = (const int*)d_in[29];
    const int* emi_item = (const int*)d_in[30];
    const int* tgt_item = (const int*)d_in[31];
    float* out = (float*)d_out;

    cudaFuncSetAttribute(k_tower, cudaFuncAttributeMaxDynamicSharedMemorySize, TOW_SMEM);
    cudaFuncSetAttribute(k_normsem, cudaFuncAttributeMaxDynamicSharedMemorySize, NSEM_SMEM);
    cudaFuncSetAttribute(k_final, cudaFuncAttributeMaxDynamicSharedMemorySize, KF_SMEM);

    void* p_s; void* p_ret; void* p_sem;
    cudaGetSymbolAddress(&p_s, g_s);
    cudaGetSymbolAddress(&p_ret, g_ret);
    cudaGetSymbolAddress(&p_sem, g_sem);
    cudaMemsetAsync(p_s, 0, 4 * BATCH * NHEAD * sizeof(float), 0);
    cudaMemsetAsync(p_ret, 0, (size_t)4 * BATCH * HID * sizeof(float), 0);
    cudaMemsetAsync(p_sem, 0, 4 * sizeof(float), 0);

    k_fr<<<1, 128>>>(r_vec);

    dim3 tg((N0_NODES + TOW_BM - 1) / TOW_BM, 2);
    k_tower<<<tg, 256, TOW_SMEM>>>(feats0, feats1,
        t0_pw, t0_pb, t0_w2, t0_b2, t0_g, t0_be,
        t1_pw, t1_pb, t1_w2, t1_b2, t1_g, t1_be,
        idx0, idx1);

    dim3 mg(E_CNT / 16, 4);
    k_metapath<<<mg, 256>>>(emi_user, tgt_user, emi_item, tgt_item, attn_user, attn_item);

    dim3 ng(BATCH / NSEM_BB, 4);
    k_normsem<<<ng, 256, NSEM_SMEM>>>(su_w1, su_b1, su_w2, si_w1, si_b1, si_w2);

    k_final<<<BATCH / KF_BB, 128, KF_SMEM>>>(cw1, cb1, cw2, out);
}

// round 8
// speedup vs baseline: 1.1973x; 1.1384x over previous
#include <cuda_runtime.h>
#include <cuda_bf16.h>
#include <math.h>

// ---------------- problem constants ----------------
#define N0_NODES 20000
#define N_ALL    40000
#define F0_DIM   512
#define HID      64
#define NHEAD    8
#define E_CNT    200000
#define BATCH    8192
#define AV_DIM   128
#define CH_DIM   128

typedef unsigned long long ull;

__device__ __forceinline__ ull pack2(float lo, float hi) {
    ull r; asm("mov.b64 %0, {%1, %2};" : "=l"(r) : "f"(lo), "f"(hi)); return r;
}
__device__ __forceinline__ void unpack2(ull v, float& lo, float& hi) {
    asm("mov.b64 {%0, %1}, %2;" : "=f"(lo), "=f"(hi) : "l"(v));
}
__device__ __forceinline__ void ffma2(ull& d, ull a, ull b) {
    asm("fma.rn.f32x2 %0, %1, %2, %0;" : "+l"(d) : "l"(a), "l"(b));
}
__device__ __forceinline__ ull fadd2(ull a, ull b) {
    ull r; asm("add.rn.f32x2 %0, %1, %2;" : "=l"(r) : "l"(a), "l"(b)); return r;
}
__device__ __forceinline__ float tanh_fast(float x) {
    float y; asm("tanh.approx.f32 %0, %1;" : "=f"(y) : "f"(x)); return y;
}
__device__ __forceinline__ void cpa16(unsigned dst, const float* src, bool valid) {
    int sz = valid ? 16 : 0;
    asm volatile("cp.async.cg.shared.global [%0], [%1], 16, %2;" :: "r"(dst), "l"(src), "r"(sz));
}
#define CP_COMMIT() asm volatile("cp.async.commit_group;")
#define CP_WAIT1()  asm volatile("cp.async.wait_group 1;")
#define CP_WAIT0()  asm volatile("cp.async.wait_group 0;")

// ---------------- device scratch ----------------
__device__ __align__(16) float g_feat[N_ALL * HID];
__device__ __align__(16) float g_fr[4 * 3 * HID];
__device__ __align__(16) float g_s[4 * BATCH * NHEAD];
__device__ __align__(16) float g_ret[4 * BATCH * HID];
__device__ __align__(16) float g_mpout[4 * BATCH * HID];
__device__ __align__(16) float g_sem[4];

// ---------------- rotation precompute ----------------
__global__ void k_fr(const float* __restrict__ r_vec) {
    int tid = threadIdx.x;
    if (tid >= 128) return;
    int mp = tid >> 5, c = tid & 31;
    int et0 = (mp < 2) ? 0 : 1;
    int et1 = (mp < 2) ? 1 : 0;

    float x0 = r_vec[(et1 >> 1) * 64 + 2 * c], y0 = r_vec[(et1 >> 1) * 64 + 2 * c + 1];
    float n = rsqrtf(x0 * x0 + y0 * y0);
    float f1re = x0 * n, f1im = (et1 & 1) ? -y0 * n : y0 * n;

    float x1 = r_vec[(et0 >> 1) * 64 + 2 * c], y1 = r_vec[(et0 >> 1) * 64 + 2 * c + 1];
    n = rsqrtf(x1 * x1 + y1 * y1);
    float r0re = x1 * n, r0im = (et0 & 1) ? -y1 * n : y1 * n;

    float f0re = f1re * r0re - f1im * r0im;
    float f0im = f1re * r0im + f1im * r0re;

    float* base = g_fr + mp * (3 * HID);
    base[0 * HID + 2 * c] = f0re; base[0 * HID + 2 * c + 1] = f0im;
    base[1 * HID + 2 * c] = f1re; base[1 * HID + 2 * c + 1] = f1im;
    base[2 * HID + 2 * c] = 1.f;  base[2 * HID + 2 * c + 1] = 0.f;
}

// ---------------- feature towers: cp.async pipelined, f32x2 register-tiled ----------------
#define TOW_BM   128
#define XS_PITCH 68
#define XS_SZ    (TOW_BM * XS_PITCH)
#define WS_SZ    (64 * 64)
#define TOW_SMEM ((2 * XS_SZ + 2 * WS_SZ) * 4)

__device__ __forceinline__ float gelu_exact(float z) {
    return 0.5f * z * (1.f + erff(z * 0.70710678118654752f));
}

__global__ void __launch_bounds__(256, 2) k_tower(
    const float* __restrict__ f0, const float* __restrict__ f1,
    const float* __restrict__ pw0, const float* __restrict__ pb0,
    const float* __restrict__ w20, const float* __restrict__ b20,
    const float* __restrict__ gm0, const float* __restrict__ be0,
    const float* __restrict__ pw1, const float* __restrict__ pb1,
    const float* __restrict__ w21, const float* __restrict__ b21,
    const float* __restrict__ gm1, const float* __restrict__ be1,
    const int* __restrict__ idx0, const int* __restrict__ idx1)
{
    int t = blockIdx.y;
    const float* feats = t ? f1  : f0;
    const float* pw    = t ? pw1 : pw0;
    const float* pb    = t ? pb1 : pb0;
    const float* w2    = t ? w21 : w20;
    const float* b2    = t ? b21 : b20;
    const float* gmw   = t ? gm1 : gm0;
    const float* bew   = t ? be1 : be0;
    const int*   idx   = t ? idx1 : idx0;

    extern __shared__ float sm[];
    float* xsp[2] = { sm, sm + XS_SZ };
    float* wsp[2] = { sm + 2 * XS_SZ, sm + 2 * XS_SZ + WS_SZ };
    unsigned smem_u32 = (unsigned)__cvta_generic_to_shared(sm);
    unsigned xsa[2] = { smem_u32, smem_u32 + XS_SZ * 4 };
    unsigned wsa[2] = { smem_u32 + 2 * XS_SZ * 4, smem_u32 + (2 * XS_SZ + WS_SZ) * 4 };

    int tid = threadIdx.x;
    int tx = tid & 15, ty = tid >> 4;
    int nb = blockIdx.x * TOW_BM;

    auto prefetch = [&](int kc, int b) {
        #pragma unroll
        for (int r = 0; r < 8; ++r) {
            int i = tid + r * 256;
            int node = i >> 4, kq = i & 15;
            int ng = nb + node;
            cpa16(xsa[b] + (unsigned)(node * XS_PITCH + kq * 4) * 4,
                  feats + (size_t)ng * F0_DIM + kc + kq * 4, ng < N0_NODES);
        }
        #pragma unroll
        for (int r = 0; r < 4; ++r) {
            int i = tid + r * 256;
            int k = i >> 4, cq = i & 15;
            cpa16(wsa[b] + (unsigned)(k * 64 + cq * 4) * 4,
                  pw + (size_t)(kc + k) * HID + cq * 4, true);
        }
        CP_COMMIT();
    };

    float4 pbv = *(const float4*)(pb + tx * 4);
    ull acc[4][4];
    #pragma unroll
    for (int i = 0; i < 4; ++i) {
        acc[i][0] = pack2(pbv.x, pbv.x);
        acc[i][1] = pack2(pbv.y, pbv.y);
        acc[i][2] = pack2(pbv.z, pbv.z);
        acc[i][3] = pack2(pbv.w, pbv.w);
    }

    prefetch(0, 0);

    for (int c = 0; c < 8; ++c) {
        int b = c & 1;
        if (c < 7) { prefetch((c + 1) * 64, b ^ 1); CP_WAIT1(); }
        else       { CP_WAIT0(); }
        __syncthreads();

        const float* xs = xsp[b];
        const float* ws = wsp[b];
        #pragma unroll 4
        for (int k = 0; k < 64; ++k) {
            float4 wv = *(const float4*)(ws + k * 64 + tx * 4);
            ull w0 = pack2(wv.x, wv.x), w1 = pack2(wv.y, wv.y);
            ull w2p = pack2(wv.z, wv.z), w3 = pack2(wv.w, wv.w);
            #pragma unroll
            for (int i = 0; i < 4; ++i) {
                int row = ty * 8 + 2 * i;
                ull xv = pack2(xs[row * XS_PITCH + k], xs[(row + 1) * XS_PITCH + k]);
                ffma2(acc[i][0], xv, w0);
                ffma2(acc[i][1], xv, w1);
                ffma2(acc[i][2], xv, w2p);
                ffma2(acc[i][3], xv, w3);
            }
        }
        __syncthreads();
    }

    #pragma unroll
    for (int r = 0; r < 4; ++r) {
        int i = tid + r * 256;
        int k = i >> 4, cq = i & 15;
        cpa16(wsa[0] + (unsigned)(k * 64 + cq * 4) * 4, w2 + (size_t)k * HID + cq * 4, true);
    }
    CP_COMMIT();

    #pragma unroll
    for (int i = 0; i < 4; ++i)
        #pragma unroll
        for (int j = 0; j < 4; ++j) {
            float zl, zh;
            unpack2(acc[i][j], zl, zh);
            int row = ty * 8 + 2 * i, col = tx * 4 + j;
            xsp[0][row * XS_PITCH + col] = gelu_exact(zl);
            xsp[0][(row + 1) * XS_PITCH + col] = gelu_exact(zh);
        }
    CP_WAIT0();
    __syncthreads();

    float4 b2v = *(const float4*)(b2 + tx * 4);
    ull yacc[4][4];
    #pragma unroll
    for (int i = 0; i < 4; ++i) {
        yacc[i][0] = fadd2(acc[i][0], pack2(b2v.x, b2v.x));
        yacc[i][1] = fadd2(acc[i][1], pack2(b2v.y, b2v.y));
        yacc[i][2] = fadd2(acc[i][2], pack2(b2v.z, b2v.z));
        yacc[i][3] = fadd2(acc[i][3], pack2(b2v.w, b2v.w));
    }
    {
        const float* xs = xsp[0];
        const float* ws = wsp[0];
        #pragma unroll 4
        for (int k = 0; k < 64; ++k) {
            float4 wv = *(const float4*)(ws + k * 64 + tx * 4);
            ull w0 = pack2(wv.x, wv.x), w1 = pack2(wv.y, wv.y);
            ull w2p = pack2(wv.z, wv.z), w3 = pack2(wv.w, wv.w);
            #pragma unroll
            for (int i = 0; i < 4; ++i) {
                int row = ty * 8 + 2 * i;
                ull xv = pack2(xs[row * XS_PITCH + k], xs[(row + 1) * XS_PITCH + k]);
                ffma2(yacc[i][0], xv, w0);
                ffma2(yacc[i][1], xv, w1);
                ffma2(yacc[i][2], xv, w2p);
                ffma2(yacc[i][3], xv, w3);
            }
        }
    }

    float y[8][4];
    #pragma unroll
    for (int i = 0; i < 4; ++i)
        #pragma unroll
        for (int j = 0; j < 4; ++j)
            unpack2(yacc[i][j], y[2 * i][j], y[2 * i + 1][j]);

    float4 gv = *(const float4*)(gmw + tx * 4);
    float4 bev = *(const float4*)(bew + tx * 4);

    #pragma unroll
    for (int i = 0; i < 8; ++i) {
        float s1 = y[i][0] + y[i][1] + y[i][2] + y[i][3];
        float s2 = y[i][0] * y[i][0] + y[i][1] * y[i][1] + y[i][2] * y[i][2] + y[i][3] * y[i][3];
        #pragma unroll
        for (int o = 8; o > 0; o >>= 1) {
            s1 += __shfl_xor_sync(0xffffffffu, s1, o);
            s2 += __shfl_xor_sync(0xffffffffu, s2, o);
        }
        float mu  = s1 * (1.f / 64.f);
        float var = s2 * (1.f / 64.f) - mu * mu;
        float rs  = rsqrtf(var + 1e-5f);
        int ng = nb + ty * 8 + i;
        if (ng < N0_NODES) {
            int dst = idx[ng];
            float4 o4;
            o4.x = (y[i][0] - mu) * rs * gv.x + bev.x;
            o4.y = (y[i][1] - mu) * rs * gv.y + bev.y;
            o4.z = (y[i][2] - mu) * rs * gv.z + bev.z;
            o4.w = (y[i][3] - mu) * rs * gv.w + bev.w;
            *(float4*)(g_feat + (size_t)dst * HID + tx * 4) = o4;
        }
    }
}

// ---------------- metapath gather: 2 instances per thread for MLP ----------------
__global__ void k_metapath(
    const int* __restrict__ emi_u, const int* __restrict__ tgt_u,
    const int* __restrict__ emi_i, const int* __restrict__ tgt_i,
    const float* __restrict__ attn_u, const float* __restrict__ attn_i)
{
    int mp = blockIdx.y;
    const int*   emi  = (mp < 2 ? emi_u : emi_i) + (size_t)(mp & 1) * E_CNT * 3;
    const int*   tgt  = (mp < 2 ? tgt_u : tgt_i) + (size_t)(mp & 1) * E_CNT;
    const float* attn = (mp < 2 ? attn_u : attn_i) + (mp & 1) * HID;

    int tid  = threadIdx.x;
    int sub  = tid & 15;
    int instA = blockIdx.x * 16 + (tid >> 4);   // grid.x = E_CNT/32
    int instB = instA + E_CNT / 2;

    const float4* fr4 = (const float4*)g_fr + mp * 48;
    float4 fr0 = fr4[sub], fr1 = fr4[16 + sub], fr2 = fr4[32 + sub];
    float4 av = ((const float4*)attn)[sub];

    // issue all index loads
    int a0 = __ldg(emi + instA * 3);
    int a1 = __ldg(emi + instA * 3 + 1);
    int a2 = __ldg(emi + instA * 3 + 2);
    int b0i = __ldg(emi + instB * 3);
    int b1i = __ldg(emi + instB * 3 + 1);
    int b2i = __ldg(emi + instB * 3 + 2);
    int tA = __ldg(tgt + instA);
    int tB = __ldg(tgt + instB);

    const float4* feat4 = (const float4*)g_feat;
    // issue all 6 gathers before consuming any
    float4 vA0 = __ldg(feat4 + (size_t)a0 * 16 + sub);
    float4 vA1 = __ldg(feat4 + (size_t)a1 * 16 + sub);
    float4 vA2 = __ldg(feat4 + (size_t)a2 * 16 + sub);
    float4 vB0 = __ldg(feat4 + (size_t)b0i * 16 + sub);
    float4 vB1 = __ldg(feat4 + (size_t)b1i * 16 + sub);
    float4 vB2 = __ldg(feat4 + (size_t)b2i * 16 + sub);

    const float inv3 = (1.f / 3.f);

    // ---- instance A ----
    {
        float hx = (vA0.x * fr0.x - vA0.y * fr0.y) + (vA1.x * fr1.x - vA1.y * fr1.y) + (vA2.x * fr2.x - vA2.y * fr2.y);
        float hy = (vA0.x * fr0.y + vA0.y * fr0.x) + (vA1.x * fr1.y + vA1.y * fr1.x) + (vA2.x * fr2.y + vA2.y * fr2.x);
        float hz = (vA0.z * fr0.z - vA0.w * fr0.w) + (vA1.z * fr1.z - vA1.w * fr1.w) + (vA2.z * fr2.z - vA2.w * fr2.w);
        float hw = (vA0.z * fr0.w + vA0.w * fr0.z) + (vA1.z * fr1.w + vA1.w * fr1.z) + (vA2.z * fr2.w + vA2.w * fr2.z);
        hx *= inv3; hy *= inv3; hz *= inv3; hw *= inv3;

        float p = hx * av.x + hy * av.y + hz * av.z + hw * av.w;
        p += __shfl_xor_sync(0xffffffffu, p, 1);
        float e = p > 0.f ? p : 0.01f * p;
        float a = expf(e);

        size_t base = (size_t)mp * BATCH + tA;
        if (!(sub & 1)) atomicAdd(&g_s[base * NHEAD + (sub >> 1)], a);
        float* rb = g_ret + base * HID + sub * 4;
        asm volatile("red.global.add.v4.f32 [%0], {%1, %2, %3, %4};"
                     :: "l"(rb), "f"(a * hx), "f"(a * hy), "f"(a * hz), "f"(a * hw)
                     : "memory");
    }
    // ---- instance B ----
    {
        float hx = (vB0.x * fr0.x - vB0.y * fr0.y) + (vB1.x * fr1.x - vB1.y * fr1.y) + (vB2.x * fr2.x - vB2.y * fr2.y);
        float hy = (vB0.x * fr0.y + vB0.y * fr0.x) + (vB1.x * fr1.y + vB1.y * fr1.x) + (vB2.x * fr2.y + vB2.y * fr2.x);
        float hz = (vB0.z * fr0.z - vB0.w * fr0.w) + (vB1.z * fr1.z - vB1.w * fr1.w) + (vB2.z * fr2.z - vB2.w * fr2.w);
        float hw = (vB0.z * fr0.w + vB0.w * fr0.z) + (vB1.z * fr1.w + vB1.w * fr1.z) + (vB2.z * fr2.w + vB2.w * fr2.z);
        hx *= inv3; hy *= inv3; hz *= inv3; hw *= inv3;

        float p = hx * av.x + hy * av.y + hz * av.z + hw * av.w;
        p += __shfl_xor_sync(0xffffffffu, p, 1);
        float e = p > 0.f ? p : 0.01f * p;
        float a = expf(e);

        size_t base = (size_t)mp * BATCH + tB;
        if (!(sub & 1)) atomicAdd(&g_s[base * NHEAD + (sub >> 1)], a);
        float* rb = g_ret + base * HID + sub * 4;
        asm volatile("red.global.add.v4.f32 [%0], {%1, %2, %3, %4};"
                     :: "l"(rb), "f"(a * hx), "f"(a * hy), "f"(a * hz), "f"(a * hw)
                     : "memory");
    }
}

// ---------------- fused normalize+elu+mpout + semantic GEMV (high occupancy) ----------------
// grid (BATCH/32, 4), block 256. Thread: bl = tid&31 (row), ch = tid>>5 (16-col chunk).
#define NSEM_BB  32
#define NSEM_BBP 33
#define NSEM_SMEM ((HID * AV_DIM + HID * NSEM_BBP) * 4)
__global__ void __launch_bounds__(256) k_normsem(
    const float* __restrict__ su_w1, const float* __restrict__ su_b1, const float* __restrict__ su_w2,
    const float* __restrict__ si_w1, const float* __restrict__ si_b1, const float* __restrict__ si_w2)
{
    int mp = blockIdx.y, tid = threadIdx.x;
    extern __shared__ float dsm[];
    float* w1s = dsm;                  // [k][c] 64x128
    float* hs  = dsm + HID * AV_DIM;   // [k][bl] 64x33
    __shared__ float rbuf[8];

    const float* w1 = (mp < 2) ? su_w1 : si_w1;
    const float* b1 = (mp < 2) ? su_b1 : si_b1;
    const float* w2 = (mp < 2) ? su_w2 : si_w2;

    for (int i = tid; i < HID * AV_DIM; i += 256) w1s[i] = w1[i];

    int b0 = blockIdx.x * NSEM_BB;
    // phase 1: v = elu(ret/s); write mpout; stage transposed (coalesced read, padded store)
    #pragma unroll
    for (int r = 0; r < 8; ++r) {
        int i = tid + r * 256;
        int bl = i >> 6, k = i & 63;
        size_t row = (size_t)mp * BATCH + b0 + bl;
        float sv = g_s[row * NHEAD + (k >> 3)];
        float v = g_ret[row * HID + k] / (sv + 1e-9f);
        v = v > 0.f ? v : expf(v) - 1.f;
        g_mpout[row * HID + k] = v;
        hs[k * NSEM_BBP + bl] = v;
    }
    __syncthreads();

    // phase 2: each thread: row bl, 16 cols [c0, c0+16)
    int bl = tid & 31, ch = tid >> 5;
    int c0 = ch * 16;
    float ssum = 0.f;
    #pragma unroll
    for (int cc = 0; cc < 16; cc += 4) {
        int c = c0 + cc;
        float4 bv = __ldg((const float4*)(b1 + c));
        float a0 = bv.x, a1 = bv.y, a2 = bv.z, a3 = bv.w;
        #pragma unroll 8
        for (int k = 0; k < HID; ++k) {
            float xv = hs[k * NSEM_BBP + bl];
            float4 wv = *(const float4*)(w1s + k * AV_DIM + c);
            a0 = fmaf(xv, wv.x, a0);
            a1 = fmaf(xv, wv.y, a1);
            a2 = fmaf(xv, wv.z, a2);
            a3 = fmaf(xv, wv.w, a3);
        }
        float4 w2v = __ldg((const float4*)(w2 + c));
        ssum += tanh_fast(a0) * w2v.x + tanh_fast(a1) * w2v.y
              + tanh_fast(a2) * w2v.z + tanh_fast(a3) * w2v.w;
    }
    #pragma unroll
    for (int o = 16; o > 0; o >>= 1) ssum += __shfl_xor_sync(0xffffffffu, ssum, o);
    if ((tid & 31) == 0) rbuf[tid >> 5] = ssum;
    __syncthreads();
    if (tid == 0) {
        float t = rbuf[0] + rbuf[1] + rbuf[2] + rbuf[3] + rbuf[4] + rbuf[5] + rbuf[6] + rbuf[7];
        atomicAdd(&g_sem[mp], t);
    }
}

// ---------------- semantic fusion + product MLP + softmax (high occupancy) ----------------
// grid BATCH/32, block 256. Thread: bl = tid&31, ch = tid>>5 (16 cols).
#define KF_BB  32
#define KF_BBP 33
#define KF_SMEM ((HID * CH_DIM + HID * KF_BBP + 2 * 8 * KF_BB) * 4)
__global__ void __launch_bounds__(256) k_final(
    const float* __restrict__ cw1, const float* __restrict__ cb1,
    const float* __restrict__ cw2, float* __restrict__ out)
{
    int tid = threadIdx.x;
    extern __shared__ float dsm[];
    float* cw1s = dsm;                       // [k][c] 64x128
    float* xs   = dsm + HID * CH_DIM;        // [k][bl] 64x33
    float* pl0  = xs + HID * KF_BBP;         // [8][32]
    float* pl1  = pl0 + 8 * KF_BB;           // [8][32]

    for (int i = tid; i < HID * CH_DIM; i += 256) cw1s[i] = cw1[i];

    float s0 = g_sem[0] * (1.f / BATCH), s1 = g_sem[1] * (1.f / BATCH);
    float s2 = g_sem[2] * (1.f / BATCH), s3 = g_sem[3] * (1.f / BATCH);
    float mU = fmaxf(s0, s1), mI = fmaxf(s2, s3);
    float e0 = expf(s0 - mU), e1 = expf(s1 - mU);
    float e2 = expf(s2 - mI), e3 = expf(s3 - mI);
    float bu0 = e0 / (e0 + e1), bu1 = e1 / (e0 + e1);
    float bi0 = e2 / (e2 + e3), bi1 = e3 / (e2 + e3);

    int b0 = blockIdx.x * KF_BB;
    #pragma unroll
    for (int r = 0; r < 8; ++r) {
        int i = tid + r * 256;
        int bl = i >> 6, k = i & 63;
        size_t b = b0 + bl;
        float hu = bu0 * g_mpout[((size_t)0 * BATCH + b) * HID + k]
                 + bu1 * g_mpout[((size_t)1 * BATCH + b) * HID + k];
        float hi = bi0 * g_mpout[((size_t)2 * BATCH + b) * HID + k]
                 + bi1 * g_mpout[((size_t)3 * BATCH + b) * HID + k];
        xs[k * KF_BBP + bl] = hu * hi;
    }
    __syncthreads();

    int bl = tid & 31, ch = tid >> 5;
    int c0 = ch * 16;
    float l0 = 0.f, l1 = 0.f;
    #pragma unroll
    for (int cc = 0; cc < 16; cc += 4) {
        int c = c0 + cc;
        float4 bv = __ldg((const float4*)(cb1 + c));
        float a0 = bv.x, a1 = bv.y, a2 = bv.z, a3 = bv.w;
        #pragma unroll 8
        for (int k = 0; k < HID; ++k) {
            float xv = xs[k * KF_BBP + bl];
            float4 wv = *(const float4*)(cw1s + k * CH_DIM + c);
            a0 = fmaf(xv, wv.x, a0);
            a1 = fmaf(xv, wv.y, a1);
            a2 = fmaf(xv, wv.z, a2);
            a3 = fmaf(xv, wv.w, a3);
        }
        a0 = fmaxf(a0, 0.f); a1 = fmaxf(a1, 0.f);
        a2 = fmaxf(a2, 0.f); a3 = fmaxf(a3, 0.f);
        float4 wa = __ldg((const float4*)(cw2 + 2 * c));
        float4 wb = __ldg((const float4*)(cw2 + 2 * c + 4));
        l0 += a0 * wa.x + a1 * wa.z + a2 * wb.x + a3 * wb.z;
        l1 += a0 * wa.y + a1 * wa.w + a2 * wb.y + a3 * wb.w;
    }
    pl0[ch * KF_BB + bl] = l0;
    pl1[ch * KF_BB + bl] = l1;
    __syncthreads();
    if (ch == 0) {
        float L0 = 0.f, L1 = 0.f;
        #pragma unroll
        for (int c = 0; c < 8; ++c) { L0 += pl0[c * KF_BB + bl]; L1 += pl1[c * KF_BB + bl]; }
        float m = fmaxf(L0, L1);
        float a0 = expf(L0 - m), a1 = expf(L1 - m);
        float inv = 1.f / (a0 + a1);
        out[(b0 + bl) * 2 + 0] = a0 * inv;
        out[(b0 + bl) * 2 + 1] = a1 * inv;
    }
}

// ---------------- launch ----------------
extern "C" void kernel_launch(void* const* d_in, const int* in_sizes, int n_in,
                              void* d_out, int out_size) {
    (void)in_sizes; (void)n_in; (void)out_size;
    const float* feats0 = (const float*)d_in[0];
    const float* feats1 = (const float*)d_in[1];
    const float* t0_pw = (const float*)d_in[2];
    const float* t0_pb = (const float*)d_in[3];
    const float* t0_w2 = (const float*)d_in[4];
    const float* t0_b2 = (const float*)d_in[5];
    const float* t0_g  = (const float*)d_in[6];
    const float* t0_be = (const float*)d_in[7];
    const float* t1_pw = (const float*)d_in[8];
    const float* t1_pb = (const float*)d_in[9];
    const float* t1_w2 = (const float*)d_in[10];
    const float* t1_b2 = (const float*)d_in[11];
    const float* t1_g  = (const float*)d_in[12];
    const float* t1_be = (const float*)d_in[13];
    const float* r_vec = (const float*)d_in[14];
    const float* attn_user = (const float*)d_in[15];
    const float* attn_item = (const float*)d_in[16];
    const float* su_w1 = (const float*)d_in[17];
    const float* su_b1 = (const float*)d_in[18];
    const float* su_w2 = (const float*)d_in[19];
    const float* si_w1 = (const float*)d_in[20];
    const float* si_b1 = (const float*)d_in[21];
    const float* si_w2 = (const float*)d_in[22];
    const float* cw1   = (const float*)d_in[23];
    const float* cb1   = (const float*)d_in[24];
    const float* cw2   = (const float*)d_in[25];
    const int* idx0 = (const int*)d_in[26];
    const int* idx1 = (const int*)d_in[27];
    const int* emi_user = (const int*)d_in[28];
    const int* tgt_user = (const int*)d_in[29];
    const int* emi_item = (const int*)d_in[30];
    const int* tgt_item = (const int*)d_in[31];
    float* out = (float*)d_out;

    cudaFuncSetAttribute(k_tower, cudaFuncAttributeMaxDynamicSharedMemorySize, TOW_SMEM);
    cudaFuncSetAttribute(k_normsem, cudaFuncAttributeMaxDynamicSharedMemorySize, NSEM_SMEM);
    cudaFuncSetAttribute(k_final, cudaFuncAttributeMaxDynamicSharedMemorySize, KF_SMEM);

    void* p_s; void* p_ret; void* p_sem;
    cudaGetSymbolAddress(&p_s, g_s);
    cudaGetSymbolAddress(&p_ret, g_ret);
    cudaGetSymbolAddress(&p_sem, g_sem);
    cudaMemsetAsync(p_s, 0, 4 * BATCH * NHEAD * sizeof(float), 0);
    cudaMemsetAsync(p_ret, 0, (size_t)4 * BATCH * HID * sizeof(float), 0);
    cudaMemsetAsync(p_sem, 0, 4 * sizeof(float), 0);

    k_fr<<<1, 128>>>(r_vec);

    dim3 tg((N0_NODES + TOW_BM - 1) / TOW_BM, 2);
    k_tower<<<tg, 256, TOW_SMEM>>>(feats0, feats1,
        t0_pw, t0_pb, t0_w2, t0_b2, t0_g, t0_be,
        t1_pw, t1_pb, t1_w2, t1_b2, t1_g, t1_be,
        idx0, idx1);

    dim3 mg(E_CNT / 32, 4);
    k_metapath<<<mg, 256>>>(emi_user, tgt_user, emi_item, tgt_item, attn_user, attn_item);

    dim3 ng(BATCH / NSEM_BB, 4);
    k_normsem<<<ng, 256, NSEM_SMEM>>>(su_w1, su_b1, su_w2, si_w1, si_b1, si_w2);

    k_final<<<BATCH / KF_BB, 256, KF_SMEM>>>(cw1, cb1, cw2, out);
}

// round 9
// speedup vs baseline: 1.2138x; 1.0138x over previous
#include <cuda_runtime.h>
#include <cuda_bf16.h>
#include <math.h>

// ---------------- problem constants ----------------
#define N0_NODES 20000
#define N_ALL    40000
#define F0_DIM   512
#define HID      64
#define NHEAD    8
#define E_CNT    200000
#define BATCH    8192
#define AV_DIM   128
#define CH_DIM   128

typedef unsigned long long ull;

__device__ __forceinline__ ull pack2(float lo, float hi) {
    ull r; asm("mov.b64 %0, {%1, %2};" : "=l"(r) : "f"(lo), "f"(hi)); return r;
}
__device__ __forceinline__ void unpack2(ull v, float& lo, float& hi) {
    asm("mov.b64 {%0, %1}, %2;" : "=f"(lo), "=f"(hi) : "l"(v));
}
__device__ __forceinline__ void ffma2(ull& d, ull a, ull b) {
    asm("fma.rn.f32x2 %0, %1, %2, %0;" : "+l"(d) : "l"(a), "l"(b));
}
__device__ __forceinline__ ull fadd2(ull a, ull b) {
    ull r; asm("add.rn.f32x2 %0, %1, %2;" : "=l"(r) : "l"(a), "l"(b)); return r;
}
__device__ __forceinline__ float tanh_fast(float x) {
    float y; asm("tanh.approx.f32 %0, %1;" : "=f"(y) : "f"(x)); return y;
}
__device__ __forceinline__ void cpa16(unsigned dst, const float* src, bool valid) {
    int sz = valid ? 16 : 0;
    asm volatile("cp.async.cg.shared.global [%0], [%1], 16, %2;" :: "r"(dst), "l"(src), "r"(sz));
}
#define CP_COMMIT() asm volatile("cp.async.commit_group;")
#define CP_WAIT1()  asm volatile("cp.async.wait_group 1;")
#define CP_WAIT0()  asm volatile("cp.async.wait_group 0;")

// ---------------- device scratch ----------------
__device__ __align__(16) float g_feat[N_ALL * HID];
__device__ __align__(16) float g_fr[4 * 3 * HID];
__device__ __align__(16) float g_s[4 * BATCH * NHEAD];
__device__ __align__(16) float g_ret[4 * BATCH * HID];
__device__ __align__(16) float g_mpout[4 * BATCH * HID];
__device__ __align__(16) float g_sem[4];

// ---------------- rotation precompute ----------------
__global__ void k_fr(const float* __restrict__ r_vec) {
    int tid = threadIdx.x;
    if (tid >= 128) return;
    int mp = tid >> 5, c = tid & 31;
    int et0 = (mp < 2) ? 0 : 1;
    int et1 = (mp < 2) ? 1 : 0;

    float x0 = r_vec[(et1 >> 1) * 64 + 2 * c], y0 = r_vec[(et1 >> 1) * 64 + 2 * c + 1];
    float n = rsqrtf(x0 * x0 + y0 * y0);
    float f1re = x0 * n, f1im = (et1 & 1) ? -y0 * n : y0 * n;

    float x1 = r_vec[(et0 >> 1) * 64 + 2 * c], y1 = r_vec[(et0 >> 1) * 64 + 2 * c + 1];
    n = rsqrtf(x1 * x1 + y1 * y1);
    float r0re = x1 * n, r0im = (et0 & 1) ? -y1 * n : y1 * n;

    float f0re = f1re * r0re - f1im * r0im;
    float f0im = f1re * r0im + f1im * r0re;

    float* base = g_fr + mp * (3 * HID);
    base[0 * HID + 2 * c] = f0re; base[0 * HID + 2 * c + 1] = f0im;
    base[1 * HID + 2 * c] = f1re; base[1 * HID + 2 * c + 1] = f1im;
    base[2 * HID + 2 * c] = 1.f;  base[2 * HID + 2 * c + 1] = 0.f;
}

// ---------------- feature towers: cp.async pipelined, f32x2 register-tiled ----------------
#define TOW_BM   128
#define XS_PITCH 68
#define XS_SZ    (TOW_BM * XS_PITCH)
#define WS_SZ    (64 * 64)
#define TOW_SMEM ((2 * XS_SZ + 2 * WS_SZ) * 4)

__device__ __forceinline__ float gelu_exact(float z) {
    return 0.5f * z * (1.f + erff(z * 0.70710678118654752f));
}

__global__ void __launch_bounds__(256, 2) k_tower(
    const float* __restrict__ f0, const float* __restrict__ f1,
    const float* __restrict__ pw0, const float* __restrict__ pb0,
    const float* __restrict__ w20, const float* __restrict__ b20,
    const float* __restrict__ gm0, const float* __restrict__ be0,
    const float* __restrict__ pw1, const float* __restrict__ pb1,
    const float* __restrict__ w21, const float* __restrict__ b21,
    const float* __restrict__ gm1, const float* __restrict__ be1,
    const int* __restrict__ idx0, const int* __restrict__ idx1)
{
    int t = blockIdx.y;
    const float* feats = t ? f1  : f0;
    const float* pw    = t ? pw1 : pw0;
    const float* pb    = t ? pb1 : pb0;
    const float* w2    = t ? w21 : w20;
    const float* b2    = t ? b21 : b20;
    const float* gmw   = t ? gm1 : gm0;
    const float* bew   = t ? be1 : be0;
    const int*   idx   = t ? idx1 : idx0;

    extern __shared__ float sm[];
    float* xsp[2] = { sm, sm + XS_SZ };
    float* wsp[2] = { sm + 2 * XS_SZ, sm + 2 * XS_SZ + WS_SZ };
    unsigned smem_u32 = (unsigned)__cvta_generic_to_shared(sm);
    unsigned xsa[2] = { smem_u32, smem_u32 + XS_SZ * 4 };
    unsigned wsa[2] = { smem_u32 + 2 * XS_SZ * 4, smem_u32 + (2 * XS_SZ + WS_SZ) * 4 };

    int tid = threadIdx.x;
    int tx = tid & 15, ty = tid >> 4;
    int nb = blockIdx.x * TOW_BM;

    auto prefetch = [&](int kc, int b) {
        #pragma unroll
        for (int r = 0; r < 8; ++r) {
            int i = tid + r * 256;
            int node = i >> 4, kq = i & 15;
            int ng = nb + node;
            cpa16(xsa[b] + (unsigned)(node * XS_PITCH + kq * 4) * 4,
                  feats + (size_t)ng * F0_DIM + kc + kq * 4, ng < N0_NODES);
        }
        #pragma unroll
        for (int r = 0; r < 4; ++r) {
            int i = tid + r * 256;
            int k = i >> 4, cq = i & 15;
            cpa16(wsa[b] + (unsigned)(k * 64 + cq * 4) * 4,
                  pw + (size_t)(kc + k) * HID + cq * 4, true);
        }
        CP_COMMIT();
    };

    float4 pbv = *(const float4*)(pb + tx * 4);
    ull acc[4][4];
    #pragma unroll
    for (int i = 0; i < 4; ++i) {
        acc[i][0] = pack2(pbv.x, pbv.x);
        acc[i][1] = pack2(pbv.y, pbv.y);
        acc[i][2] = pack2(pbv.z, pbv.z);
        acc[i][3] = pack2(pbv.w, pbv.w);
    }

    prefetch(0, 0);

    for (int c = 0; c < 8; ++c) {
        int b = c & 1;
        if (c < 7) { prefetch((c + 1) * 64, b ^ 1); CP_WAIT1(); }
        else       { CP_WAIT0(); }
        __syncthreads();

        const float* xs = xsp[b];
        const float* ws = wsp[b];
        #pragma unroll 4
        for (int k = 0; k < 64; ++k) {
            float4 wv = *(const float4*)(ws + k * 64 + tx * 4);
            ull w0 = pack2(wv.x, wv.x), w1 = pack2(wv.y, wv.y);
            ull w2p = pack2(wv.z, wv.z), w3 = pack2(wv.w, wv.w);
            #pragma unroll
            for (int i = 0; i < 4; ++i) {
                int row = ty * 8 + 2 * i;
                ull xv = pack2(xs[row * XS_PITCH + k], xs[(row + 1) * XS_PITCH + k]);
                ffma2(acc[i][0], xv, w0);
                ffma2(acc[i][1], xv, w1);
                ffma2(acc[i][2], xv, w2p);
                ffma2(acc[i][3], xv, w3);
            }
        }
        __syncthreads();
    }

    #pragma unroll
    for (int r = 0; r < 4; ++r) {
        int i = tid + r * 256;
        int k = i >> 4, cq = i & 15;
        cpa16(wsa[0] + (unsigned)(k * 64 + cq * 4) * 4, w2 + (size_t)k * HID + cq * 4, true);
    }
    CP_COMMIT();

    #pragma unroll
    for (int i = 0; i < 4; ++i)
        #pragma unroll
        for (int j = 0; j < 4; ++j) {
            float zl, zh;
            unpack2(acc[i][j], zl, zh);
            int row = ty * 8 + 2 * i, col = tx * 4 + j;
            xsp[0][row * XS_PITCH + col] = gelu_exact(zl);
            xsp[0][(row + 1) * XS_PITCH + col] = gelu_exact(zh);
        }
    CP_WAIT0();
    __syncthreads();

    float4 b2v = *(const float4*)(b2 + tx * 4);
    ull yacc[4][4];
    #pragma unroll
    for (int i = 0; i < 4; ++i) {
        yacc[i][0] = fadd2(acc[i][0], pack2(b2v.x, b2v.x));
        yacc[i][1] = fadd2(acc[i][1], pack2(b2v.y, b2v.y));
        yacc[i][2] = fadd2(acc[i][2], pack2(b2v.z, b2v.z));
        yacc[i][3] = fadd2(acc[i][3], pack2(b2v.w, b2v.w));
    }
    {
        const float* xs = xsp[0];
        const float* ws = wsp[0];
        #pragma unroll 4
        for (int k = 0; k < 64; ++k) {
            float4 wv = *(const float4*)(ws + k * 64 + tx * 4);
            ull w0 = pack2(wv.x, wv.x), w1 = pack2(wv.y, wv.y);
            ull w2p = pack2(wv.z, wv.z), w3 = pack2(wv.w, wv.w);
            #pragma unroll
            for (int i = 0; i < 4; ++i) {
                int row = ty * 8 + 2 * i;
                ull xv = pack2(xs[row * XS_PITCH + k], xs[(row + 1) * XS_PITCH + k]);
                ffma2(yacc[i][0], xv, w0);
                ffma2(yacc[i][1], xv, w1);
                ffma2(yacc[i][2], xv, w2p);
                ffma2(yacc[i][3], xv, w3);
            }
        }
    }

    float y[8][4];
    #pragma unroll
    for (int i = 0; i < 4; ++i)
        #pragma unroll
        for (int j = 0; j < 4; ++j)
            unpack2(yacc[i][j], y[2 * i][j], y[2 * i + 1][j]);

    float4 gv = *(const float4*)(gmw + tx * 4);
    float4 bev = *(const float4*)(bew + tx * 4);

    #pragma unroll
    for (int i = 0; i < 8; ++i) {
        float s1 = y[i][0] + y[i][1] + y[i][2] + y[i][3];
        float s2 = y[i][0] * y[i][0] + y[i][1] * y[i][1] + y[i][2] * y[i][2] + y[i][3] * y[i][3];
        #pragma unroll
        for (int o = 8; o > 0; o >>= 1) {
            s1 += __shfl_xor_sync(0xffffffffu, s1, o);
            s2 += __shfl_xor_sync(0xffffffffu, s2, o);
        }
        float mu  = s1 * (1.f / 64.f);
        float var = s2 * (1.f / 64.f) - mu * mu;
        float rs  = rsqrtf(var + 1e-5f);
        int ng = nb + ty * 8 + i;
        if (ng < N0_NODES) {
            int dst = idx[ng];
            float4 o4;
            o4.x = (y[i][0] - mu) * rs * gv.x + bev.x;
            o4.y = (y[i][1] - mu) * rs * gv.y + bev.y;
            o4.z = (y[i][2] - mu) * rs * gv.z + bev.z;
            o4.w = (y[i][3] - mu) * rs * gv.w + bev.w;
            *(float4*)(g_feat + (size_t)dst * HID + tx * 4) = o4;
        }
    }
}

// ---------------- metapath gather (per-mp launch): 2 instances per thread ----------------
__global__ void k_metapath(
    int mp,
    const int* __restrict__ emi, const int* __restrict__ tgt,
    const float* __restrict__ attn)
{
    int tid  = threadIdx.x;
    int sub  = tid & 15;
    int instA = blockIdx.x * 16 + (tid >> 4);   // grid.x = E_CNT/32
    int instB = instA + E_CNT / 2;

    const float4* fr4 = (const float4*)g_fr + mp * 48;
    float4 fr0 = fr4[sub], fr1 = fr4[16 + sub], fr2 = fr4[32 + sub];
    float4 av = ((const float4*)attn)[sub];

    int a0 = __ldg(emi + instA * 3);
    int a1 = __ldg(emi + instA * 3 + 1);
    int a2 = __ldg(emi + instA * 3 + 2);
    int b0i = __ldg(emi + instB * 3);
    int b1i = __ldg(emi + instB * 3 + 1);
    int b2i = __ldg(emi + instB * 3 + 2);
    int tA = __ldg(tgt + instA);
    int tB = __ldg(tgt + instB);

    const float4* feat4 = (const float4*)g_feat;
    float4 vA0 = __ldg(feat4 + (size_t)a0 * 16 + sub);
    float4 vA1 = __ldg(feat4 + (size_t)a1 * 16 + sub);
    float4 vA2 = __ldg(feat4 + (size_t)a2 * 16 + sub);
    float4 vB0 = __ldg(feat4 + (size_t)b0i * 16 + sub);
    float4 vB1 = __ldg(feat4 + (size_t)b1i * 16 + sub);
    float4 vB2 = __ldg(feat4 + (size_t)b2i * 16 + sub);

    const float inv3 = (1.f / 3.f);

    {
        float hx = (vA0.x * fr0.x - vA0.y * fr0.y) + (vA1.x * fr1.x - vA1.y * fr1.y) + (vA2.x * fr2.x - vA2.y * fr2.y);
        float hy = (vA0.x * fr0.y + vA0.y * fr0.x) + (vA1.x * fr1.y + vA1.y * fr1.x) + (vA2.x * fr2.y + vA2.y * fr2.x);
        float hz = (vA0.z * fr0.z - vA0.w * fr0.w) + (vA1.z * fr1.z - vA1.w * fr1.w) + (vA2.z * fr2.z - vA2.w * fr2.w);
        float hw = (vA0.z * fr0.w + vA0.w * fr0.z) + (vA1.z * fr1.w + vA1.w * fr1.z) + (vA2.z * fr2.w + vA2.w * fr2.z);
        hx *= inv3; hy *= inv3; hz *= inv3; hw *= inv3;

        float p = hx * av.x + hy * av.y + hz * av.z + hw * av.w;
        p += __shfl_xor_sync(0xffffffffu, p, 1);
        float e = p > 0.f ? p : 0.01f * p;
        float a = expf(e);

        size_t base = (size_t)mp * BATCH + tA;
        if (!(sub & 1)) atomicAdd(&g_s[base * NHEAD + (sub >> 1)], a);
        float* rb = g_ret + base * HID + sub * 4;
        asm volatile("red.global.add.v4.f32 [%0], {%1, %2, %3, %4};"
                     :: "l"(rb), "f"(a * hx), "f"(a * hy), "f"(a * hz), "f"(a * hw)
                     : "memory");
    }
    {
        float hx = (vB0.x * fr0.x - vB0.y * fr0.y) + (vB1.x * fr1.x - vB1.y * fr1.y) + (vB2.x * fr2.x - vB2.y * fr2.y);
        float hy = (vB0.x * fr0.y + vB0.y * fr0.x) + (vB1.x * fr1.y + vB1.y * fr1.x) + (vB2.x * fr2.y + vB2.y * fr2.x);
        float hz = (vB0.z * fr0.z - vB0.w * fr0.w) + (vB1.z * fr1.z - vB1.w * fr1.w) + (vB2.z * fr2.z - vB2.w * fr2.w);
        float hw = (vB0.z * fr0.w + vB0.w * fr0.z) + (vB1.z * fr1.w + vB1.w * fr1.z) + (vB2.z * fr2.w + vB2.w * fr2.z);
        hx *= inv3; hy *= inv3; hz *= inv3; hw *= inv3;

        float p = hx * av.x + hy * av.y + hz * av.z + hw * av.w;
        p += __shfl_xor_sync(0xffffffffu, p, 1);
        float e = p > 0.f ? p : 0.01f * p;
        float a = expf(e);

        size_t base = (size_t)mp * BATCH + tB;
        if (!(sub & 1)) atomicAdd(&g_s[base * NHEAD + (sub >> 1)], a);
        float* rb = g_ret + base * HID + sub * 4;
        asm volatile("red.global.add.v4.f32 [%0], {%1, %2, %3, %4};"
                     :: "l"(rb), "f"(a * hx), "f"(a * hy), "f"(a * hz), "f"(a * hw)
                     : "memory");
    }
}

// ---------------- fused normalize+elu+mpout + semantic GEMV (col-pair f32x2) ----------------
// per-mp launch. grid BATCH/32, block 256. Thread: bl=tid&31 (row), ch=tid>>5 (16 cols = 8 pairs).
#define NSEM_BB  32
#define NSEM_BBP 33
#define NSEM_SMEM ((HID * AV_DIM + HID * NSEM_BBP) * 4)
__global__ void __launch_bounds__(256) k_normsem(
    int mp,
    const float* __restrict__ w1, const float* __restrict__ b1, const float* __restrict__ w2)
{
    int tid = threadIdx.x;
    extern __shared__ float dsm[];
    float* w1s = dsm;                  // [k][c] 64x128
    float* hs  = dsm + HID * AV_DIM;   // [k][bl] 64x33
    __shared__ float rbuf[8];

    for (int i = tid; i < HID * AV_DIM; i += 256) w1s[i] = w1[i];

    int b0 = blockIdx.x * NSEM_BB;
    #pragma unroll
    for (int r = 0; r < 8; ++r) {
        int i = tid + r * 256;
        int bl = i >> 6, k = i & 63;
        size_t row = (size_t)mp * BATCH + b0 + bl;
        float sv = g_s[row * NHEAD + (k >> 3)];
        float v = g_ret[row * HID + k] / (sv + 1e-9f);
        v = v > 0.f ? v : expf(v) - 1.f;
        g_mpout[row * HID + k] = v;
        hs[k * NSEM_BBP + bl] = v;
    }
    __syncthreads();

    int bl = tid & 31, ch = tid >> 5;
    int c0 = ch * 16;
    ull accp[8];
    {
        float4 ba = __ldg((const float4*)(b1 + c0));
        float4 bb = __ldg((const float4*)(b1 + c0 + 4));
        float4 bc = __ldg((const float4*)(b1 + c0 + 8));
        float4 bd = __ldg((const float4*)(b1 + c0 + 12));
        accp[0] = pack2(ba.x, ba.y); accp[1] = pack2(ba.z, ba.w);
        accp[2] = pack2(bb.x, bb.y); accp[3] = pack2(bb.z, bb.w);
        accp[4] = pack2(bc.x, bc.y); accp[5] = pack2(bc.z, bc.w);
        accp[6] = pack2(bd.x, bd.y); accp[7] = pack2(bd.z, bd.w);
    }
    #pragma unroll 4
    for (int k = 0; k < HID; ++k) {
        float xv = hs[k * NSEM_BBP + bl];
        ull xvp = pack2(xv, xv);
        const float4* wr = (const float4*)(w1s + k * AV_DIM + c0);
        float4 wv0 = wr[0], wv1 = wr[1], wv2 = wr[2], wv3 = wr[3];
        ffma2(accp[0], xvp, pack2(wv0.x, wv0.y));
        ffma2(accp[1], xvp, pack2(wv0.z, wv0.w));
        ffma2(accp[2], xvp, pack2(wv1.x, wv1.y));
        ffma2(accp[3], xvp, pack2(wv1.z, wv1.w));
        ffma2(accp[4], xvp, pack2(wv2.x, wv2.y));
        ffma2(accp[5], xvp, pack2(wv2.z, wv2.w));
        ffma2(accp[6], xvp, pack2(wv3.x, wv3.y));
        ffma2(accp[7], xvp, pack2(wv3.z, wv3.w));
    }
    float ssum = 0.f;
    {
        float4 wa = __ldg((const float4*)(w2 + c0));
        float4 wb = __ldg((const float4*)(w2 + c0 + 4));
        float4 wc = __ldg((const float4*)(w2 + c0 + 8));
        float4 wd = __ldg((const float4*)(w2 + c0 + 12));
        float lo, hi;
        unpack2(accp[0], lo, hi); ssum += tanh_fast(lo) * wa.x + tanh_fast(hi) * wa.y;
        unpack2(accp[1], lo, hi); ssum += tanh_fast(lo) * wa.z + tanh_fast(hi) * wa.w;
        unpack2(accp[2], lo, hi); ssum += tanh_fast(lo) * wb.x + tanh_fast(hi) * wb.y;
        unpack2(accp[3], lo, hi); ssum += tanh_fast(lo) * wb.z + tanh_fast(hi) * wb.w;
        unpack2(accp[4], lo, hi); ssum += tanh_fast(lo) * wc.x + tanh_fast(hi) * wc.y;
        unpack2(accp[5], lo, hi); ssum += tanh_fast(lo) * wc.z + tanh_fast(hi) * wc.w;
        unpack2(accp[6], lo, hi); ssum += tanh_fast(lo) * wd.x + tanh_fast(hi) * wd.y;
        unpack2(accp[7], lo, hi); ssum += tanh_fast(lo) * wd.z + tanh_fast(hi) * wd.w;
    }
    #pragma unroll
    for (int o = 16; o > 0; o >>= 1) ssum += __shfl_xor_sync(0xffffffffu, ssum, o);
    if ((tid & 31) == 0) rbuf[tid >> 5] = ssum;
    __syncthreads();
    if (tid == 0) {
        float t = rbuf[0] + rbuf[1] + rbuf[2] + rbuf[3] + rbuf[4] + rbuf[5] + rbuf[6] + rbuf[7];
        atomicAdd(&g_sem[mp], t);
    }
}

// ---------------- semantic fusion + product MLP + softmax ----------------
#define KF_BB  32
#define KF_BBP 33
#define KF_SMEM ((HID * CH_DIM + HID * KF_BBP + 2 * 8 * KF_BB) * 4)
__global__ void __launch_bounds__(256) k_final(
    const float* __restrict__ cw1, const float* __restrict__ cb1,
    const float* __restrict__ cw2, float* __restrict__ out)
{
    int tid = threadIdx.x;
    extern __shared__ float dsm[];
    float* cw1s = dsm;                       // [k][c] 64x128
    float* xs   = dsm + HID * CH_DIM;        // [k][bl] 64x33
    float* pl0  = xs + HID * KF_BBP;         // [8][32]
    float* pl1  = pl0 + 8 * KF_BB;           // [8][32]

    for (int i = tid; i < HID * CH_DIM; i += 256) cw1s[i] = cw1[i];

    float s0 = g_sem[0] * (1.f / BATCH), s1 = g_sem[1] * (1.f / BATCH);
    float s2 = g_sem[2] * (1.f / BATCH), s3 = g_sem[3] * (1.f / BATCH);
    float mU = fmaxf(s0, s1), mI = fmaxf(s2, s3);
    float e0 = expf(s0 - mU), e1 = expf(s1 - mU);
    float e2 = expf(s2 - mI), e3 = expf(s3 - mI);
    float bu0 = e0 / (e0 + e1), bu1 = e1 / (e0 + e1);
    float bi0 = e2 / (e2 + e3), bi1 = e3 / (e2 + e3);

    int b0 = blockIdx.x * KF_BB;
    #pragma unroll
    for (int r = 0; r < 8; ++r) {
        int i = tid + r * 256;
        int bl = i >> 6, k = i & 63;
        size_t b = b0 + bl;
        float hu = bu0 * g_mpout[((size_t)0 * BATCH + b) * HID + k]
                 + bu1 * g_mpout[((size_t)1 * BATCH + b) * HID + k];
        float hi = bi0 * g_mpout[((size_t)2 * BATCH + b) * HID + k]
                 + bi1 * g_mpout[((size_t)3 * BATCH + b) * HID + k];
        xs[k * KF_BBP + bl] = hu * hi;
    }
    __syncthreads();

    int bl = tid & 31, ch = tid >> 5;
    int c0 = ch * 16;
    float l0 = 0.f, l1 = 0.f;
    #pragma unroll
    for (int cc = 0; cc < 16; cc += 4) {
        int c = c0 + cc;
        float4 bv = __ldg((const float4*)(cb1 + c));
        float a0 = bv.x, a1 = bv.y, a2 = bv.z, a3 = bv.w;
        #pragma unroll 8
        for (int k = 0; k < HID; ++k) {
            float xv = xs[k * KF_BBP + bl];
            float4 wv = *(const float4*)(cw1s + k * CH_DIM + c);
            a0 = fmaf(xv, wv.x, a0);
            a1 = fmaf(xv, wv.y, a1);
            a2 = fmaf(xv, wv.z, a2);
            a3 = fmaf(xv, wv.w, a3);
        }
        a0 = fmaxf(a0, 0.f); a1 = fmaxf(a1, 0.f);
        a2 = fmaxf(a2, 0.f); a3 = fmaxf(a3, 0.f);
        float4 wa = __ldg((const float4*)(cw2 + 2 * c));
        float4 wb = __ldg((const float4*)(cw2 + 2 * c + 4));
        l0 += a0 * wa.x + a1 * wa.z + a2 * wb.x + a3 * wb.z;
        l1 += a0 * wa.y + a1 * wa.w + a2 * wb.y + a3 * wb.w;
    }
    pl0[ch * KF_BB + bl] = l0;
    pl1[ch * KF_BB + bl] = l1;
    __syncthreads();
    if (ch == 0) {
        float L0 = 0.f, L1 = 0.f;
        #pragma unroll
        for (int c = 0; c < 8; ++c) { L0 += pl0[c * KF_BB + bl]; L1 += pl1[c * KF_BB + bl]; }
        float m = fmaxf(L0, L1);
        float a0 = expf(L0 - m), a1 = expf(L1 - m);
        float inv = 1.f / (a0 + a1);
        out[(b0 + bl) * 2 + 0] = a0 * inv;
        out[(b0 + bl) * 2 + 1] = a1 * inv;
    }
}

// ---------------- launch (2-stream pipeline, capture-fork pattern) ----------------
extern "C" void kernel_launch(void* const* d_in, const int* in_sizes, int n_in,
                              void* d_out, int out_size) {
    (void)in_sizes; (void)n_in; (void)out_size;
    const float* feats0 = (const float*)d_in[0];
    const float* feats1 = (const float*)d_in[1];
    const float* t0_pw = (const float*)d_in[2];
    const float* t0_pb = (const float*)d_in[3];
    const float* t0_w2 = (const float*)d_in[4];
    const float* t0_b2 = (const float*)d_in[5];
    const float* t0_g  = (const float*)d_in[6];
    const float* t0_be = (const float*)d_in[7];
    const float* t1_pw = (const float*)d_in[8];
    const float* t1_pb = (const float*)d_in[9];
    const float* t1_w2 = (const float*)d_in[10];
    const float* t1_b2 = (const float*)d_in[11];
    const float* t1_g  = (const float*)d_in[12];
    const float* t1_be = (const float*)d_in[13];
    const float* r_vec = (const float*)d_in[14];
    const float* attn_user = (const float*)d_in[15];
    const float* attn_item = (const float*)d_in[16];
    const float* su_w1 = (const float*)d_in[17];
    const float* su_b1 = (const float*)d_in[18];
    const float* su_w2 = (const float*)d_in[19];
    const float* si_w1 = (const float*)d_in[20];
    const float* si_b1 = (const float*)d_in[21];
    const float* si_w2 = (const float*)d_in[22];
    const float* cw1   = (const float*)d_in[23];
    const float* cb1   = (const float*)d_in[24];
    const float* cw2   = (const float*)d_in[25];
    const int* idx0 = (const int*)d_in[26];
    const int* idx1 = (const int*)d_in[27];
    const int* emi_user = (const int*)d_in[28];
    const int* tgt_user = (const int*)d_in[29];
    const int* emi_item = (const int*)d_in[30];
    const int* tgt_item = (const int*)d_in[31];
    float* out = (float*)d_out;

    static cudaStream_t s1 = nullptr;
    static cudaEvent_t evRoot = nullptr, evPre = nullptr, evTow = nullptr, evS1 = nullptr;
    if (!s1) {
        cudaStreamCreateWithFlags(&s1, cudaStreamNonBlocking);
        cudaEventCreateWithFlags(&evRoot, cudaEventDisableTiming);
        cudaEventCreateWithFlags(&evPre,  cudaEventDisableTiming);
        cudaEventCreateWithFlags(&evTow,  cudaEventDisableTiming);
        cudaEventCreateWithFlags(&evS1,   cudaEventDisableTiming);
        cudaFuncSetAttribute(k_tower, cudaFuncAttributeMaxDynamicSharedMemorySize, TOW_SMEM);
        cudaFuncSetAttribute(k_normsem, cudaFuncAttributeMaxDynamicSharedMemorySize, NSEM_SMEM);
        cudaFuncSetAttribute(k_final, cudaFuncAttributeMaxDynamicSharedMemorySize, KF_SMEM);
    }

    void* p_s; void* p_ret; void* p_sem;
    cudaGetSymbolAddress(&p_s, g_s);
    cudaGetSymbolAddress(&p_ret, g_ret);
    cudaGetSymbolAddress(&p_sem, g_sem);

    // fork side stream from trunk
    cudaEventRecord(evRoot, 0);
    cudaStreamWaitEvent(s1, evRoot, 0);

    // side stream: accumulator zeroing + rotation precompute (overlaps tower)
    cudaMemsetAsync(p_s, 0, 4 * BATCH * NHEAD * sizeof(float), s1);
    cudaMemsetAsync(p_ret, 0, (size_t)4 * BATCH * HID * sizeof(float), s1);
    cudaMemsetAsync(p_sem, 0, 4 * sizeof(float), s1);
    k_fr<<<1, 128, 0, s1>>>(r_vec);
    cudaEventRecord(evPre, s1);

    // trunk: towers
    dim3 tg((N0_NODES + TOW_BM - 1) / TOW_BM, 2);
    k_tower<<<tg, 256, TOW_SMEM, 0>>>(feats0, feats1,
        t0_pw, t0_pb, t0_w2, t0_b2, t0_g, t0_be,
        t1_pw, t1_pb, t1_w2, t1_b2, t1_g, t1_be,
        idx0, idx1);

    // join prereqs on trunk, then broadcast to side stream
    cudaStreamWaitEvent(0, evPre, 0);
    cudaEventRecord(evTow, 0);
    cudaStreamWaitEvent(s1, evTow, 0);

    // per-mp metapath/normsem chains on two streams
    const int* emiP[4] = { emi_user, emi_user + (size_t)E_CNT * 3, emi_item, emi_item + (size_t)E_CNT * 3 };
    const int* tgtP[4] = { tgt_user, tgt_user + E_CNT, tgt_item, tgt_item + E_CNT };
    const float* attnP[4] = { attn_user, attn_user + HID, attn_item, attn_item + HID };
    const float* w1P[4] = { su_w1, su_w1, si_w1, si_w1 };
    const float* b1P[4] = { su_b1, su_b1, si_b1, si_b1 };
    const float* w2P[4] = { su_w2, su_w2, si_w2, si_w2 };

    dim3 mg(E_CNT / 32);
    dim3 ng(BATCH / NSEM_BB);
    for (int mp = 0; mp < 4; ++mp) {
        cudaStream_t st = (mp & 1) ? s1 : (cudaStream_t)0;
        k_metapath<<<mg, 256, 0, st>>>(mp, emiP[mp], tgtP[mp], attnP[mp]);
        k_normsem<<<ng, 256, NSEM_SMEM, st>>>(mp, w1P[mp], b1P[mp], w2P[mp]);
    }

    // join side stream, final on trunk
    cudaEventRecord(evS1, s1);
    cudaStreamWaitEvent(0, evS1, 0);
    k_final<<<BATCH / KF_BB, 256, KF_SMEM, 0>>>(cw1, cb1, cw2, out);
}